// round 2
// baseline (speedup 1.0000x reference)
#include <cuda_runtime.h>
#include <math.h>

#define IT 20
#define NB 4
#define GH 480
#define GW 640
#define SH 120
#define SW 160
#define NC 32

// ---------------- static device scratch (no runtime allocation) ----------------
__device__ float g_xt[NB*GH*GW*NC];                 // x transposed to NHWC  (157 MB)
__device__ float g_dt[NB*SH*SW*NC];                 // d transposed to NHWC  (9.8 MB)
__device__ float g_rg[IT*NB*SH*SW];                 // pooled gt
__device__ float g_ixb[IT*NB*SH*SW];                // sample x pixel coord
__device__ float g_iyb[IT*NB*SH*SW];                // sample y pixel coord
__device__ float g_feat[IT*NB*SH*SW*NC];            // sampled features NHWC (196 MB)
__device__ float g_attd[IT*NB*SH*SW*NC];            // sigmoid(conv)*d NHWC  (196 MB)
__device__ float g_num[IT];
__device__ float g_den[IT];

// ---------------- zero per-iteration accumulators ----------------
__global__ void zero_kernel() {
    int t = threadIdx.x;
    if (t < IT) { g_num[t] = 0.0f; g_den[t] = 0.0f; }
}

// ---------------- NCHW -> NHWC transpose (C=32), per batch ----------------
__global__ void transpose_kernel(const float* __restrict__ src, float* __restrict__ dst, int S) {
    __shared__ float t[32][33];
    int s0 = blockIdx.x * 32;
    const float* sb = src + (size_t)blockIdx.y * NC * S;
    float*       db = dst + (size_t)blockIdx.y * S * NC;
    int lx = threadIdx.x, ly = threadIdx.y;
    #pragma unroll
    for (int cc = 0; cc < 4; cc++) {
        int c = ly + cc * 8;
        t[c][lx] = sb[(size_t)c * S + s0 + lx];
    }
    __syncthreads();
    #pragma unroll
    for (int cc = 0; cc < 4; cc++) {
        int sr = ly + cc * 8;
        db[(size_t)(s0 + sr) * NC + lx] = t[lx][sr];
    }
}

// ---------------- random pooling + sample-coordinate computation ----------------
__global__ void pool_kernel(const float* __restrict__ gts, const float* __restrict__ rnd) {
    int tid = blockIdx.x * blockDim.x + threadIdx.x;
    if (tid >= IT*NB*SH*SW) return;
    int x  = tid % SW;  int t1 = tid / SW;
    int y  = t1 % SH;   int t2 = t1 / SH;
    int b  = t2 % NB;   int it = t2 / NB;
    const float* gp = gts + b * GH * GW;
    const float* rp = rnd + (it * NB + b) * GH * GW;

    float best = -1.0f;            // all rm >= 0, so first element always taken;
    int srow = y*4, scol = x*4;    // strict > keeps first occurrence (matches argmax)
    #pragma unroll
    for (int bi = 0; bi < 4; bi++) {
        int row = y*4 + bi;
        #pragma unroll
        for (int bj = 0; bj < 4; bj++) {
            int col = x*4 + bj;
            float g  = gp[row*GW + col];
            float rm = (g > 0.1f) ? rp[row*GW + col] : 0.0f;
            if (rm > best) { best = rm; srow = row; scol = col; }
        }
    }
    float rv = gp[srow*GW + scol];
    if (rv < 0.1f) rv = 0.0f;
    g_rg[tid] = rv;

    int index = srow*GW + scol + 1282;   // bias = W//w//2 + (H//h//2)*W = 2 + 2*640
    float fx = (float)(index % GW);
    float fy = (float)(index / GW);
    float gx = 2.0f * (fx / (float)GW - 0.5f);
    float gy = 2.0f * (fy / (float)GH - 0.5f);
    g_ixb[tid] = (gx + 1.0f) * 0.5f * (float)(GW - 1);
    g_iyb[tid] = (gy + 1.0f) * 0.5f * (float)(GH - 1);
}

// ---------------- bilinear grid-sample: one warp per point, lane = channel ----------------
__global__ void sample_kernel() {
    int gt  = blockIdx.x * blockDim.x + threadIdx.x;
    int pid = gt >> 5;
    int lane = gt & 31;
    if (pid >= IT*NB*SH*SW) return;
    float ix = g_ixb[pid], iy = g_iyb[pid];
    float x0f = floorf(ix), y0f = floorf(iy);
    float wx = ix - x0f, wy = iy - y0f;
    int x0 = (int)x0f, y0 = (int)y0f;
    int b = (pid / (SH*SW)) % NB;
    const float* xb = g_xt + b * GH * GW * NC;
    float acc = 0.0f;
#define CORNER(XC, YC, WG) {                                            \
        int xc = (XC), yc = (YC);                                       \
        bool v = (xc >= 0) && (xc <= GW-1) && (yc >= 0) && (yc <= GH-1);\
        int xi = min(max(xc, 0), GW-1);                                 \
        int yi = min(max(yc, 0), GH-1);                                 \
        float val = xb[(yi*GW + xi)*NC + lane];                         \
        acc += val * (v ? (WG) : 0.0f);                                 \
    }
    CORNER(x0,   y0,   (1.0f-wx)*(1.0f-wy));
    CORNER(x0+1, y0,   wx*(1.0f-wy));
    CORNER(x0,   y0+1, (1.0f-wx)*wy);
    CORNER(x0+1, y0+1, wx*wy);
#undef CORNER
    g_feat[pid*NC + lane] = acc;
}

// ---------------- conv3x3 (32->32) + sigmoid, fused *d -> attd (NHWC) ----------------
__global__ __launch_bounds__(256) void conv_att_kernel(const float* __restrict__ Watt,
                                                       const float* __restrict__ batt) {
    __shared__ float s_tile[10][34][17];   // +1 pad: conflict-free taps
    __shared__ float s_w[9][16][32];       // [k][ci][co] for float4 co loads
    int tx = threadIdx.x, ty = threadIdx.y;
    int tid = ty * 32 + tx;
    int z  = blockIdx.z;                   // it*NB + b
    int gy = blockIdx.y * 8 + ty;
    int gx = blockIdx.x * 32 + tx;
    int gy0 = blockIdx.y * 8 - 1;
    int gx0 = blockIdx.x * 32 - 1;

    float acc[32];
    #pragma unroll
    for (int i = 0; i < 32; i++) acc[i] = 0.0f;

    const float* fz = g_feat + z * SH * SW * NC;

    for (int cc = 0; cc < 2; cc++) {
        __syncthreads();
        // tile load (16 channels)
        for (int idx = tid; idx < 10*34*16; idx += 256) {
            int ci = idx & 15; int rem = idx >> 4;
            int xx = rem % 34; int yy = rem / 34;
            int ggy = gy0 + yy, ggx = gx0 + xx;
            float v = 0.0f;
            if (ggy >= 0 && ggy < SH && ggx >= 0 && ggx < SW)
                v = fz[(ggy*SW + ggx)*NC + cc*16 + ci];
            s_tile[yy][xx][ci] = v;
        }
        // weight load: Watt[co][ci][ky][kx] -> s_w[k][ci][co]
        for (int idx = tid; idx < 9*16*32; idx += 256) {
            int co = idx & 31; int rem = idx >> 5;
            int ci = rem % 16; int k = rem / 16;
            s_w[k][ci][co] = Watt[(co*32 + cc*16 + ci)*9 + k];
        }
        __syncthreads();

        #pragma unroll 2
        for (int ci = 0; ci < 16; ci++) {
            float t[9];
            #pragma unroll
            for (int ky = 0; ky < 3; ky++)
                #pragma unroll
                for (int kx = 0; kx < 3; kx++)
                    t[ky*3+kx] = s_tile[ty+ky][tx+kx][ci];
            #pragma unroll
            for (int k = 0; k < 9; k++) {
                #pragma unroll
                for (int c4 = 0; c4 < 8; c4++) {
                    float4 wv = *(const float4*)&s_w[k][ci][c4*4];
                    acc[c4*4+0] += wv.x * t[k];
                    acc[c4*4+1] += wv.y * t[k];
                    acc[c4*4+2] += wv.z * t[k];
                    acc[c4*4+3] += wv.w * t[k];
                }
            }
        }
    }

    int b = z & 3;
    const float* dp = g_dt   + ((b*SH + gy)*SW + gx) * NC;
    float*       op = g_attd + (z*SH*SW + gy*SW + gx) * NC;
    #pragma unroll
    for (int c4 = 0; c4 < 8; c4++) {
        float4 dv = *(const float4*)&dp[c4*4];
        float4 o;
        float v0 = acc[c4*4+0] + batt[c4*4+0];
        float v1 = acc[c4*4+1] + batt[c4*4+1];
        float v2 = acc[c4*4+2] + batt[c4*4+2];
        float v3 = acc[c4*4+3] + batt[c4*4+3];
        o.x = dv.x / (1.0f + expf(-v0));
        o.y = dv.y / (1.0f + expf(-v1));
        o.z = dv.z / (1.0f + expf(-v2));
        o.w = dv.w / (1.0f + expf(-v3));
        *(float4*)&op[c4*4] = o;
    }
}

// ---------------- conv3x3 (32->4) + log-grads + masked smooth-L1 + reduction ----------------
__global__ __launch_bounds__(256) void conv_post_loss_kernel(const float* __restrict__ Wp,
                                                             const float* __restrict__ bp) {
    __shared__ float s_tile[10][34][17];
    __shared__ float s_w[9][16][4];
    __shared__ float rnum[256];
    __shared__ float rden[256];
    int tx = threadIdx.x, ty = threadIdx.y;
    int tid = ty * 32 + tx;
    int z  = blockIdx.z;
    int gy = blockIdx.y * 8 + ty;
    int gx = blockIdx.x * 32 + tx;
    int gy0 = blockIdx.y * 8 - 1;
    int gx0 = blockIdx.x * 32 - 1;

    float acc[4] = {0.0f, 0.0f, 0.0f, 0.0f};
    const float* az = g_attd + z * SH * SW * NC;

    for (int cc = 0; cc < 2; cc++) {
        __syncthreads();
        for (int idx = tid; idx < 10*34*16; idx += 256) {
            int ci = idx & 15; int rem = idx >> 4;
            int xx = rem % 34; int yy = rem / 34;
            int ggy = gy0 + yy, ggx = gx0 + xx;
            float v = 0.0f;
            if (ggy >= 0 && ggy < SH && ggx >= 0 && ggx < SW)
                v = az[(ggy*SW + ggx)*NC + cc*16 + ci];
            s_tile[yy][xx][ci] = v;
        }
        for (int idx = tid; idx < 9*16*4; idx += 256) {
            int g = idx & 3; int rem = idx >> 2;
            int ci = rem % 16; int k = rem / 16;
            s_w[k][ci][g] = Wp[(g*32 + cc*16 + ci)*9 + k];
        }
        __syncthreads();

        #pragma unroll 4
        for (int ci = 0; ci < 16; ci++) {
            float t[9];
            #pragma unroll
            for (int ky = 0; ky < 3; ky++)
                #pragma unroll
                for (int kx = 0; kx < 3; kx++)
                    t[ky*3+kx] = s_tile[ty+ky][tx+kx][ci];
            #pragma unroll
            for (int k = 0; k < 9; k++) {
                float4 wv = *(const float4*)&s_w[k][ci][0];
                acc[0] += wv.x * t[k];
                acc[1] += wv.y * t[k];
                acc[2] += wv.z * t[k];
                acc[3] += wv.w * t[k];
            }
        }
    }

    float ds[4];
    #pragma unroll
    for (int g = 0; g < 4; g++) ds[g] = acc[g] + bp[g];

    const float* rz = g_rg + z * SH * SW;
    float rv = rz[gy*SW + gx];
    float lc = logf(rv + 1e-6f);
    bool  mc = rv > 0.1f;

    const int dys[4] = {0, 1, 1, 1};
    const int dxs[4] = {1, 1, 0, -1};
    float num = 0.0f, den = 0.0f;
    #pragma unroll
    for (int g = 0; g < 4; g++) {
        int ny = gy + dys[g], nx = gx + dxs[g];
        bool inb = (ny < SH) && (nx >= 0) && (nx < SW);
        float nv = inb ? rz[ny*SW + nx] : 0.0f;
        float gg = lc - logf(nv + 1e-6f);
        float mk = (mc && (nv > 0.1f)) ? 1.0f : 0.0f;
        float a  = fabsf(ds[g] - gg);
        float sl1 = (a < 0.01f) ? (0.5f * a * a / 0.01f) : (a - 0.005f);
        num += sl1 * mk;
        den += mk;
    }
    rnum[tid] = num; rden[tid] = den;
    __syncthreads();
    for (int s = 128; s > 0; s >>= 1) {
        if (tid < s) { rnum[tid] += rnum[tid+s]; rden[tid] += rden[tid+s]; }
        __syncthreads();
    }
    if (tid == 0) {
        int it = z >> 2;
        atomicAdd(&g_num[it], rnum[0]);
        atomicAdd(&g_den[it], rden[0]);
    }
}

// ---------------- finalize: mean over iterations of num/den ----------------
__global__ void finalize_kernel(float* out) {
    if (threadIdx.x == 0 && blockIdx.x == 0) {
        float s = 0.0f;
        for (int i = 0; i < IT; i++) s += g_num[i] / g_den[i];
        out[0] = s / (float)IT;
    }
}

// ---------------- launch ----------------
extern "C" void kernel_launch(void* const* d_in, const int* in_sizes, int n_in,
                              void* d_out, int out_size) {
    const float* x    = (const float*)d_in[0];
    const float* d    = (const float*)d_in[1];
    const float* gts  = (const float*)d_in[2];
    const float* rnd  = (const float*)d_in[3];
    const float* Watt = (const float*)d_in[4];
    const float* batt = (const float*)d_in[5];
    const float* Wp   = (const float*)d_in[6];
    const float* bp   = (const float*)d_in[7];
    float* out = (float*)d_out;

    float *xt, *dt;
    cudaGetSymbolAddress((void**)&xt, g_xt);
    cudaGetSymbolAddress((void**)&dt, g_dt);

    zero_kernel<<<1, 32>>>();
    transpose_kernel<<<dim3(GH*GW/32, NB), dim3(32, 8)>>>(x, xt, GH*GW);
    transpose_kernel<<<dim3(SH*SW/32, NB), dim3(32, 8)>>>(d, dt, SH*SW);
    pool_kernel<<<(IT*NB*SH*SW + 255)/256, 256>>>(gts, rnd);
    sample_kernel<<<(IT*NB*SH*SW*32)/256, 256>>>();
    conv_att_kernel<<<dim3(SW/32, SH/8, IT*NB), dim3(32, 8)>>>(Watt, batt);
    conv_post_loss_kernel<<<dim3(SW/32, SH/8, IT*NB), dim3(32, 8)>>>(Wp, bp);
    finalize_kernel<<<1, 32>>>(out);
}

// round 3
// speedup vs baseline: 1.0270x; 1.0270x over previous
#include <cuda_runtime.h>
#include <math.h>

#define IT 20
#define NB 4
#define GH 480
#define GW 640
#define SH 120
#define SW 160
#define NC 32

typedef unsigned long long u64;

// ---------------- static device scratch (no runtime allocation) ----------------
__device__ float g_xt[NB*GH*GW*NC];                 // x transposed to NHWC  (157 MB)
__device__ float g_dt[NB*SH*SW*NC];                 // d transposed to NHWC  (9.8 MB)
__device__ float g_rg[IT*NB*SH*SW];                 // pooled gt
__device__ float g_ixb[IT*NB*SH*SW];                // sample x pixel coord
__device__ float g_iyb[IT*NB*SH*SW];                // sample y pixel coord
__device__ float g_feat[IT*NB*SH*SW*NC];            // sampled features NHWC (196 MB)
__device__ float g_attd[IT*NB*SH*SW*NC];            // sigmoid(conv)*d NHWC  (196 MB)
__device__ float g_num[IT];
__device__ float g_den[IT];

// packed f32x2 helpers (sm_100+/103a): 2 FMAs per instruction
__device__ __forceinline__ u64 pack2(float v) {
    u64 r;
    asm("mov.b64 %0, {%1, %1};" : "=l"(r) : "f"(v));
    return r;
}
__device__ __forceinline__ void fma2(u64& acc, u64 a, u64 b) {
    asm("fma.rn.f32x2 %0, %1, %2, %0;" : "+l"(acc) : "l"(a), "l"(b));
}
__device__ __forceinline__ void unpack2(u64 v, float& lo, float& hi) {
    asm("mov.b64 {%0, %1}, %2;" : "=f"(lo), "=f"(hi) : "l"(v));
}

// ---------------- zero per-iteration accumulators ----------------
__global__ void zero_kernel() {
    int t = threadIdx.x;
    if (t < IT) { g_num[t] = 0.0f; g_den[t] = 0.0f; }
}

// ---------------- NCHW -> NHWC transpose (C=32), per batch ----------------
__global__ void transpose_kernel(const float* __restrict__ src, float* __restrict__ dst, int S) {
    __shared__ float t[32][33];
    int s0 = blockIdx.x * 32;
    const float* sb = src + (size_t)blockIdx.y * NC * S;
    float*       db = dst + (size_t)blockIdx.y * S * NC;
    int lx = threadIdx.x, ly = threadIdx.y;
    #pragma unroll
    for (int cc = 0; cc < 4; cc++) {
        int c = ly + cc * 8;
        t[c][lx] = sb[(size_t)c * S + s0 + lx];
    }
    __syncthreads();
    #pragma unroll
    for (int cc = 0; cc < 4; cc++) {
        int sr = ly + cc * 8;
        db[(size_t)(s0 + sr) * NC + lx] = t[lx][sr];
    }
}

// ---------------- random pooling + sample-coordinate computation ----------------
__global__ void pool_kernel(const float* __restrict__ gts, const float* __restrict__ rnd) {
    int tid = blockIdx.x * blockDim.x + threadIdx.x;
    if (tid >= IT*NB*SH*SW) return;
    int x  = tid % SW;  int t1 = tid / SW;
    int y  = t1 % SH;   int t2 = t1 / SH;
    int b  = t2 % NB;   int it = t2 / NB;
    const float* gp = gts + b * GH * GW;
    const float* rp = rnd + (it * NB + b) * GH * GW;

    float best = -1.0f;
    int srow = y*4, scol = x*4;
    #pragma unroll
    for (int bi = 0; bi < 4; bi++) {
        int row = y*4 + bi;
        #pragma unroll
        for (int bj = 0; bj < 4; bj++) {
            int col = x*4 + bj;
            float g  = gp[row*GW + col];
            float rm = (g > 0.1f) ? rp[row*GW + col] : 0.0f;
            if (rm > best) { best = rm; srow = row; scol = col; }
        }
    }
    float rv = gp[srow*GW + scol];
    if (rv < 0.1f) rv = 0.0f;
    g_rg[tid] = rv;

    int index = srow*GW + scol + 1282;   // bias = W//w//2 + (H//h//2)*W = 2 + 2*640
    float fx = (float)(index % GW);
    float fy = (float)(index / GW);
    float gx = 2.0f * (fx / (float)GW - 0.5f);
    float gy = 2.0f * (fy / (float)GH - 0.5f);
    g_ixb[tid] = (gx + 1.0f) * 0.5f * (float)(GW - 1);
    g_iyb[tid] = (gy + 1.0f) * 0.5f * (float)(GH - 1);
}

// ---------------- bilinear grid-sample: one warp per point, lane = channel ----------------
__global__ void sample_kernel() {
    int gt  = blockIdx.x * blockDim.x + threadIdx.x;
    int pid = gt >> 5;
    int lane = gt & 31;
    if (pid >= IT*NB*SH*SW) return;
    float ix = g_ixb[pid], iy = g_iyb[pid];
    float x0f = floorf(ix), y0f = floorf(iy);
    float wx = ix - x0f, wy = iy - y0f;
    int x0 = (int)x0f, y0 = (int)y0f;
    int b = (pid / (SH*SW)) % NB;
    const float* xb = g_xt + b * GH * GW * NC;
    float acc = 0.0f;
#define CORNER(XC, YC, WG) {                                            \
        int xc = (XC), yc = (YC);                                       \
        bool v = (xc >= 0) && (xc <= GW-1) && (yc >= 0) && (yc <= GH-1);\
        int xi = min(max(xc, 0), GW-1);                                 \
        int yi = min(max(yc, 0), GH-1);                                 \
        float val = xb[(yi*GW + xi)*NC + lane];                         \
        acc += val * (v ? (WG) : 0.0f);                                 \
    }
    CORNER(x0,   y0,   (1.0f-wx)*(1.0f-wy));
    CORNER(x0+1, y0,   wx*(1.0f-wy));
    CORNER(x0,   y0+1, (1.0f-wx)*wy);
    CORNER(x0+1, y0+1, wx*wy);
#undef CORNER
    g_feat[pid*NC + lane] = acc;
}

// ---------------- conv3x3 (32->32) + sigmoid, fused *d -> attd (NHWC) ----------------
// packed f32x2: 2 output channels per accumulator
__global__ __launch_bounds__(256) void conv_att_kernel(const float* __restrict__ Watt,
                                                       const float* __restrict__ batt) {
    __shared__ __align__(16) float s_tile[10][34][17];   // +1 pad: conflict-free taps
    __shared__ __align__(16) float s_w[9][16][32];       // [k][ci][co]
    int tx = threadIdx.x, ty = threadIdx.y;
    int tid = ty * 32 + tx;
    int z  = blockIdx.z;                   // it*NB + b
    int gy = blockIdx.y * 8 + ty;
    int gx = blockIdx.x * 32 + tx;
    int gy0 = blockIdx.y * 8 - 1;
    int gx0 = blockIdx.x * 32 - 1;

    u64 acc[16];                           // 16 co-pairs
    #pragma unroll
    for (int i = 0; i < 16; i++) acc[i] = 0ULL;

    const float* fz = g_feat + z * SH * SW * NC;

    for (int cc = 0; cc < 2; cc++) {
        __syncthreads();
        // tile load (16 channels)
        for (int idx = tid; idx < 10*34*16; idx += 256) {
            int ci = idx & 15; int rem = idx >> 4;
            int xx = rem % 34; int yy = rem / 34;
            int ggy = gy0 + yy, ggx = gx0 + xx;
            float v = 0.0f;
            if (ggy >= 0 && ggy < SH && ggx >= 0 && ggx < SW)
                v = fz[(ggy*SW + ggx)*NC + cc*16 + ci];
            s_tile[yy][xx][ci] = v;
        }
        // weight load: Watt[co][ci][ky][kx] -> s_w[k][ci][co]
        for (int idx = tid; idx < 9*16*32; idx += 256) {
            int co = idx & 31; int rem = idx >> 5;
            int ci = rem % 16; int k = rem / 16;
            s_w[k][ci][co] = Watt[(co*32 + cc*16 + ci)*9 + k];
        }
        __syncthreads();

        #pragma unroll 2
        for (int ci = 0; ci < 16; ci++) {
            u64 t2[9];
            #pragma unroll
            for (int ky = 0; ky < 3; ky++)
                #pragma unroll
                for (int kx = 0; kx < 3; kx++)
                    t2[ky*3+kx] = pack2(s_tile[ty+ky][tx+kx][ci]);
            #pragma unroll
            for (int k = 0; k < 9; k++) {
                #pragma unroll
                for (int q = 0; q < 4; q++) {      // 4 x LDS.128 = 8 co-pairs... (2 pairs each)
                    ulonglong2 wv = *(const ulonglong2*)&s_w[k][ci][q*8];
                    fma2(acc[q*4+0], wv.x, t2[k]);
                    fma2(acc[q*4+1], wv.y, t2[k]);
                    ulonglong2 wv2 = *(const ulonglong2*)&s_w[k][ci][q*8+4];
                    fma2(acc[q*4+2], wv2.x, t2[k]);
                    fma2(acc[q*4+3], wv2.y, t2[k]);
                }
            }
        }
    }

    int b = z & 3;
    const float* dp = g_dt   + ((b*SH + gy)*SW + gx) * NC;
    float*       op = g_attd + (z*SH*SW + gy*SW + gx) * NC;
    #pragma unroll
    for (int c4 = 0; c4 < 8; c4++) {
        float4 dv = *(const float4*)&dp[c4*4];
        float4 o;
        float v0, v1, v2, v3;
        unpack2(acc[c4*2+0], v0, v1);
        unpack2(acc[c4*2+1], v2, v3);
        v0 += batt[c4*4+0];
        v1 += batt[c4*4+1];
        v2 += batt[c4*4+2];
        v3 += batt[c4*4+3];
        o.x = dv.x / (1.0f + expf(-v0));
        o.y = dv.y / (1.0f + expf(-v1));
        o.z = dv.z / (1.0f + expf(-v2));
        o.w = dv.w / (1.0f + expf(-v3));
        *(float4*)&op[c4*4] = o;
    }
}

// ---------------- conv3x3 (32->4) + log-grads + masked smooth-L1 + reduction ----------------
__global__ __launch_bounds__(256) void conv_post_loss_kernel(const float* __restrict__ Wp,
                                                             const float* __restrict__ bp) {
    __shared__ __align__(16) float s_tile[10][34][17];
    __shared__ __align__(16) float s_w[9][16][4];
    __shared__ float rnum[256];
    __shared__ float rden[256];
    int tx = threadIdx.x, ty = threadIdx.y;
    int tid = ty * 32 + tx;
    int z  = blockIdx.z;
    int gy = blockIdx.y * 8 + ty;
    int gx = blockIdx.x * 32 + tx;
    int gy0 = blockIdx.y * 8 - 1;
    int gx0 = blockIdx.x * 32 - 1;

    u64 acc2[2] = {0ULL, 0ULL};
    const float* az = g_attd + z * SH * SW * NC;

    for (int cc = 0; cc < 2; cc++) {
        __syncthreads();
        for (int idx = tid; idx < 10*34*16; idx += 256) {
            int ci = idx & 15; int rem = idx >> 4;
            int xx = rem % 34; int yy = rem / 34;
            int ggy = gy0 + yy, ggx = gx0 + xx;
            float v = 0.0f;
            if (ggy >= 0 && ggy < SH && ggx >= 0 && ggx < SW)
                v = az[(ggy*SW + ggx)*NC + cc*16 + ci];
            s_tile[yy][xx][ci] = v;
        }
        for (int idx = tid; idx < 9*16*4; idx += 256) {
            int g = idx & 3; int rem = idx >> 2;
            int ci = rem % 16; int k = rem / 16;
            s_w[k][ci][g] = Wp[(g*32 + cc*16 + ci)*9 + k];
        }
        __syncthreads();

        #pragma unroll 4
        for (int ci = 0; ci < 16; ci++) {
            u64 t2[9];
            #pragma unroll
            for (int ky = 0; ky < 3; ky++)
                #pragma unroll
                for (int kx = 0; kx < 3; kx++)
                    t2[ky*3+kx] = pack2(s_tile[ty+ky][tx+kx][ci]);
            #pragma unroll
            for (int k = 0; k < 9; k++) {
                ulonglong2 wv = *(const ulonglong2*)&s_w[k][ci][0];
                fma2(acc2[0], wv.x, t2[k]);
                fma2(acc2[1], wv.y, t2[k]);
            }
        }
    }

    float ds[4];
    unpack2(acc2[0], ds[0], ds[1]);
    unpack2(acc2[1], ds[2], ds[3]);
    #pragma unroll
    for (int g = 0; g < 4; g++) ds[g] += bp[g];

    const float* rz = g_rg + z * SH * SW;
    float rv = rz[gy*SW + gx];
    float lc = logf(rv + 1e-6f);
    bool  mc = rv > 0.1f;

    const int dys[4] = {0, 1, 1, 1};
    const int dxs[4] = {1, 1, 0, -1};
    float num = 0.0f, den = 0.0f;
    #pragma unroll
    for (int g = 0; g < 4; g++) {
        int ny = gy + dys[g], nx = gx + dxs[g];
        bool inb = (ny < SH) && (nx >= 0) && (nx < SW);
        float nv = inb ? rz[ny*SW + nx] : 0.0f;
        float gg = lc - logf(nv + 1e-6f);
        float mk = (mc && (nv > 0.1f)) ? 1.0f : 0.0f;
        float a  = fabsf(ds[g] - gg);
        float sl1 = (a < 0.01f) ? (0.5f * a * a / 0.01f) : (a - 0.005f);
        num += sl1 * mk;
        den += mk;
    }
    rnum[tid] = num; rden[tid] = den;
    __syncthreads();
    for (int s = 128; s > 0; s >>= 1) {
        if (tid < s) { rnum[tid] += rnum[tid+s]; rden[tid] += rden[tid+s]; }
        __syncthreads();
    }
    if (tid == 0) {
        int it = z >> 2;
        atomicAdd(&g_num[it], rnum[0]);
        atomicAdd(&g_den[it], rden[0]);
    }
}

// ---------------- finalize: mean over iterations of num/den ----------------
__global__ void finalize_kernel(float* out) {
    if (threadIdx.x == 0 && blockIdx.x == 0) {
        float s = 0.0f;
        for (int i = 0; i < IT; i++) s += g_num[i] / g_den[i];
        out[0] = s / (float)IT;
    }
}

// ---------------- launch ----------------
extern "C" void kernel_launch(void* const* d_in, const int* in_sizes, int n_in,
                              void* d_out, int out_size) {
    const float* x    = (const float*)d_in[0];
    const float* d    = (const float*)d_in[1];
    const float* gts  = (const float*)d_in[2];
    const float* rnd  = (const float*)d_in[3];
    const float* Watt = (const float*)d_in[4];
    const float* batt = (const float*)d_in[5];
    const float* Wp   = (const float*)d_in[6];
    const float* bp   = (const float*)d_in[7];
    float* out = (float*)d_out;

    float *xt, *dt;
    cudaGetSymbolAddress((void**)&xt, g_xt);
    cudaGetSymbolAddress((void**)&dt, g_dt);

    zero_kernel<<<1, 32>>>();
    transpose_kernel<<<dim3(GH*GW/32, NB), dim3(32, 8)>>>(x, xt, GH*GW);
    transpose_kernel<<<dim3(SH*SW/32, NB), dim3(32, 8)>>>(d, dt, SH*SW);
    pool_kernel<<<(IT*NB*SH*SW + 255)/256, 256>>>(gts, rnd);
    sample_kernel<<<(IT*NB*SH*SW*32)/256, 256>>>();
    conv_att_kernel<<<dim3(SW/32, SH/8, IT*NB), dim3(32, 8)>>>(Watt, batt);
    conv_post_loss_kernel<<<dim3(SW/32, SH/8, IT*NB), dim3(32, 8)>>>(Wp, bp);
    finalize_kernel<<<1, 32>>>(out);
}

// round 6
// speedup vs baseline: 1.5524x; 1.5116x over previous
#include <cuda_runtime.h>
#include <math.h>

#define IT 20
#define NB 4
#define GH 480
#define GW 640
#define SH 120
#define SW 160
#define NC 32

typedef unsigned long long u64;

// ---------------- static device scratch (no runtime allocation) ----------------
__device__ float g_xt[NB*GH*GW*NC];                 // x transposed to NHWC  (157 MB)
__device__ float g_dt[NB*SH*SW*NC];                 // d transposed to NHWC  (9.8 MB)
__device__ float g_rg[IT*NB*SH*SW];                 // pooled gt
__device__ float g_ixb[IT*NB*SH*SW];                // sample x pixel coord
__device__ float g_iyb[IT*NB*SH*SW];                // sample y pixel coord
__device__ float g_feat[IT*NB*SH*SW*NC];            // sampled features NHWC (196 MB)
__device__ float g_attd[IT*NB*SH*SW*NC];            // sigmoid(conv)*d NHWC  (196 MB)
__device__ float g_num[IT];
__device__ float g_den[IT];

// packed f32x2 helpers (sm_103a): 2 FMAs per instruction
__device__ __forceinline__ u64 pack2(float v) {
    u64 r;
    asm("mov.b64 %0, {%1, %1};" : "=l"(r) : "f"(v));
    return r;
}
__device__ __forceinline__ void fma2(u64& acc, u64 a, u64 b) {
    asm("fma.rn.f32x2 %0, %1, %2, %0;" : "+l"(acc) : "l"(a), "l"(b));
}
__device__ __forceinline__ void unpack2(u64 v, float& lo, float& hi) {
    asm("mov.b64 {%0, %1}, %2;" : "=f"(lo), "=f"(hi) : "l"(v));
}

// ---------------- zero per-iteration accumulators ----------------
__global__ void zero_kernel() {
    int t = threadIdx.x;
    if (t < IT) { g_num[t] = 0.0f; g_den[t] = 0.0f; }
}

// ---------------- NCHW -> NHWC transpose (C=32), per batch ----------------
__global__ void transpose_kernel(const float* __restrict__ src, float* __restrict__ dst, int S) {
    __shared__ float t[32][33];
    int s0 = blockIdx.x * 32;
    const float* sb = src + (size_t)blockIdx.y * NC * S;
    float*       db = dst + (size_t)blockIdx.y * S * NC;
    int lx = threadIdx.x, ly = threadIdx.y;
    #pragma unroll
    for (int cc = 0; cc < 4; cc++) {
        int c = ly + cc * 8;
        t[c][lx] = sb[(size_t)c * S + s0 + lx];
    }
    __syncthreads();
    #pragma unroll
    for (int cc = 0; cc < 4; cc++) {
        int sr = ly + cc * 8;
        db[(size_t)(s0 + sr) * NC + lx] = t[lx][sr];
    }
}

// ---------------- random pooling + sample-coordinate computation ----------------
__global__ void pool_kernel(const float* __restrict__ gts, const float* __restrict__ rnd) {
    int tid = blockIdx.x * blockDim.x + threadIdx.x;
    if (tid >= IT*NB*SH*SW) return;
    int x  = tid % SW;  int t1 = tid / SW;
    int y  = t1 % SH;   int t2 = t1 / SH;
    int b  = t2 % NB;   int it = t2 / NB;
    const float* gp = gts + b * GH * GW;
    const float* rp = rnd + (it * NB + b) * GH * GW;

    float best = -1.0f;
    int srow = y*4, scol = x*4;
    #pragma unroll
    for (int bi = 0; bi < 4; bi++) {
        int row = y*4 + bi;
        #pragma unroll
        for (int bj = 0; bj < 4; bj++) {
            int col = x*4 + bj;
            float g  = gp[row*GW + col];
            float rm = (g > 0.1f) ? rp[row*GW + col] : 0.0f;
            if (rm > best) { best = rm; srow = row; scol = col; }
        }
    }
    float rv = gp[srow*GW + scol];
    if (rv < 0.1f) rv = 0.0f;
    g_rg[tid] = rv;

    int index = srow*GW + scol + 1282;   // bias = W//w//2 + (H//h//2)*W = 2 + 2*640
    float fx = (float)(index % GW);
    float fy = (float)(index / GW);
    float gx = 2.0f * (fx / (float)GW - 0.5f);
    float gy = 2.0f * (fy / (float)GH - 0.5f);
    g_ixb[tid] = (gx + 1.0f) * 0.5f * (float)(GW - 1);
    g_iyb[tid] = (gy + 1.0f) * 0.5f * (float)(GH - 1);
}

// ---------------- bilinear grid-sample: one warp per point, lane = channel ----------------
__global__ void sample_kernel() {
    int gt  = blockIdx.x * blockDim.x + threadIdx.x;
    int pid = gt >> 5;
    int lane = gt & 31;
    if (pid >= IT*NB*SH*SW) return;
    float ix = g_ixb[pid], iy = g_iyb[pid];
    float x0f = floorf(ix), y0f = floorf(iy);
    float wx = ix - x0f, wy = iy - y0f;
    int x0 = (int)x0f, y0 = (int)y0f;
    int b = (pid / (SH*SW)) % NB;
    const float* xb = g_xt + b * GH * GW * NC;
    float acc = 0.0f;
#define CORNER(XC, YC, WG) {                                            \
        int xc = (XC), yc = (YC);                                       \
        bool v = (xc >= 0) && (xc <= GW-1) && (yc >= 0) && (yc <= GH-1);\
        int xi = min(max(xc, 0), GW-1);                                 \
        int yi = min(max(yc, 0), GH-1);                                 \
        float val = xb[(yi*GW + xi)*NC + lane];                         \
        acc += val * (v ? (WG) : 0.0f);                                 \
    }
    CORNER(x0,   y0,   (1.0f-wx)*(1.0f-wy));
    CORNER(x0+1, y0,   wx*(1.0f-wy));
    CORNER(x0,   y0+1, (1.0f-wx)*wy);
    CORNER(x0+1, y0+1, wx*wy);
#undef CORNER
    g_feat[pid*NC + lane] = acc;
}

// ---------------- conv3x3 (32->32) + sigmoid, fused *d -> attd (NHWC) ----------------
// register blocking: each thread = 2x2 pixel quad x 16 output channels (8 f32x2 pairs)
// weights LDS amortized over 4 pixels; taps shared across the quad.
__global__ __launch_bounds__(128) void conv_att_kernel(const float* __restrict__ Watt,
                                                       const float* __restrict__ batt) {
    __shared__ float s_tile[10][8][35];                  // [y][ci][x], odd stride
    __shared__ __align__(16) float s_w[9][8][32];        // [k][ci][co]
    int tid = threadIdx.x;
    int half = tid >> 6;          // 0: co 0-15, 1: co 16-31
    int q    = tid & 63;          // quad id (16 x 4)
    int qx   = (q & 15) * 2;      // interior x 0..30
    int qy   = (q >> 4) * 2;      // interior y 0..6
    int z   = blockIdx.z;
    int gx0 = blockIdx.x * 32 - 1;
    int gy0 = blockIdx.y * 8  - 1;
    const float* fz = g_feat + z * SH * SW * NC;

    u64 acc[8][4];
    #pragma unroll
    for (int i = 0; i < 8; i++)
        #pragma unroll
        for (int p = 0; p < 4; p++) acc[i][p] = 0ULL;

    for (int cc = 0; cc < 4; cc++) {
        __syncthreads();
        // tile: 10 rows x 34 cols x 8 ci
        for (int idx = tid; idx < 10*34*8; idx += 128) {
            int ci = idx & 7; int rem = idx >> 3;
            int xx = rem % 34; int yy = rem / 34;
            int ggy = gy0 + yy, ggx = gx0 + xx;
            float v = 0.0f;
            if (ggy >= 0 && ggy < SH && ggx >= 0 && ggx < SW)
                v = fz[(ggy*SW + ggx)*NC + cc*8 + ci];
            s_tile[yy][ci][xx] = v;
        }
        // weights: Watt[co][ci][k] -> s_w[k][ci][co]
        for (int idx = tid; idx < 9*8*32; idx += 128) {
            int co = idx & 31; int rem = idx >> 5;
            int ci = rem & 7;  int k = rem >> 3;
            s_w[k][ci][co] = Watt[(co*32 + cc*8 + ci)*9 + k];
        }
        __syncthreads();

        #pragma unroll 2
        for (int ci = 0; ci < 8; ci++) {
            u64 t2[4][4];
            #pragma unroll
            for (int i = 0; i < 4; i++)
                #pragma unroll
                for (int j = 0; j < 4; j++)
                    t2[i][j] = pack2(s_tile[qy + i][ci][qx + j]);
            #pragma unroll
            for (int ky = 0; ky < 3; ky++) {
                #pragma unroll
                for (int kx = 0; kx < 3; kx++) {
                    int k = ky*3 + kx;
                    ulonglong2 wa = *(const ulonglong2*)&s_w[k][ci][half*16 + 0];
                    ulonglong2 wb = *(const ulonglong2*)&s_w[k][ci][half*16 + 4];
                    ulonglong2 wc = *(const ulonglong2*)&s_w[k][ci][half*16 + 8];
                    ulonglong2 wd = *(const ulonglong2*)&s_w[k][ci][half*16 + 12];
                    u64 w[8] = {wa.x, wa.y, wb.x, wb.y, wc.x, wc.y, wd.x, wd.y};
                    #pragma unroll
                    for (int pr = 0; pr < 8; pr++) {
                        #pragma unroll
                        for (int py = 0; py < 2; py++)
                            #pragma unroll
                            for (int px = 0; px < 2; px++)
                                fma2(acc[pr][py*2 + px], w[pr], t2[py + ky][px + kx]);
                    }
                }
            }
        }
    }

    int b = z & 3;
    #pragma unroll
    for (int p = 0; p < 4; p++) {
        int py = p >> 1, px = p & 1;
        int gy = blockIdx.y*8  + qy + py;
        int gx = blockIdx.x*32 + qx + px;
        const float* dp = g_dt   + ((b*SH + gy)*SW + gx) * NC + half*16;
        float*       op = g_attd + ((size_t)z*SH*SW + gy*SW + gx) * NC + half*16;
        #pragma unroll
        for (int c4 = 0; c4 < 4; c4++) {
            float4 dv = *(const float4*)&dp[c4*4];
            float v0, v1, v2, v3;
            unpack2(acc[c4*2 + 0][p], v0, v1);
            unpack2(acc[c4*2 + 1][p], v2, v3);
            v0 += batt[half*16 + c4*4 + 0];
            v1 += batt[half*16 + c4*4 + 1];
            v2 += batt[half*16 + c4*4 + 2];
            v3 += batt[half*16 + c4*4 + 3];
            float4 o;
            o.x = dv.x / (1.0f + expf(-v0));
            o.y = dv.y / (1.0f + expf(-v1));
            o.z = dv.z / (1.0f + expf(-v2));
            o.w = dv.w / (1.0f + expf(-v3));
            *(float4*)&op[c4*4] = o;
        }
    }
}

// ---------------- conv3x3 (32->4) + log-grads + masked smooth-L1 + reduction ----------------
// same quad register blocking: thread = 2x2 pixels, all 4 output channels (2 pairs)
__global__ __launch_bounds__(64) void conv_post_loss_kernel(const float* __restrict__ Wp,
                                                            const float* __restrict__ bp) {
    __shared__ float s_tile[10][8][35];
    __shared__ __align__(16) float s_w[9][8][4];
    __shared__ float rnum[64];
    __shared__ float rden[64];
    int tid = threadIdx.x;          // 64 threads = 64 quads
    int qx  = (tid & 15) * 2;
    int qy  = (tid >> 4) * 2;
    int z   = blockIdx.z;
    int gx0 = blockIdx.x * 32 - 1;
    int gy0 = blockIdx.y * 8  - 1;
    const float* az = g_attd + (size_t)z * SH * SW * NC;

    u64 acc[2][4];
    #pragma unroll
    for (int i = 0; i < 2; i++)
        #pragma unroll
        for (int p = 0; p < 4; p++) acc[i][p] = 0ULL;

    for (int cc = 0; cc < 4; cc++) {
        __syncthreads();
        for (int idx = tid; idx < 10*34*8; idx += 64) {
            int ci = idx & 7; int rem = idx >> 3;
            int xx = rem % 34; int yy = rem / 34;
            int ggy = gy0 + yy, ggx = gx0 + xx;
            float v = 0.0f;
            if (ggy >= 0 && ggy < SH && ggx >= 0 && ggx < SW)
                v = az[(ggy*SW + ggx)*NC + cc*8 + ci];
            s_tile[yy][ci][xx] = v;
        }
        for (int idx = tid; idx < 9*8*4; idx += 64) {
            int g = idx & 3; int rem = idx >> 2;
            int ci = rem & 7; int k = rem >> 3;
            s_w[k][ci][g] = Wp[(g*32 + cc*8 + ci)*9 + k];
        }
        __syncthreads();

        #pragma unroll 2
        for (int ci = 0; ci < 8; ci++) {
            u64 t2[4][4];
            #pragma unroll
            for (int i = 0; i < 4; i++)
                #pragma unroll
                for (int j = 0; j < 4; j++)
                    t2[i][j] = pack2(s_tile[qy + i][ci][qx + j]);
            #pragma unroll
            for (int ky = 0; ky < 3; ky++) {
                #pragma unroll
                for (int kx = 0; kx < 3; kx++) {
                    int k = ky*3 + kx;
                    ulonglong2 wv = *(const ulonglong2*)&s_w[k][ci][0];
                    #pragma unroll
                    for (int py = 0; py < 2; py++)
                        #pragma unroll
                        for (int px = 0; px < 2; px++) {
                            fma2(acc[0][py*2 + px], wv.x, t2[py + ky][px + kx]);
                            fma2(acc[1][py*2 + px], wv.y, t2[py + ky][px + kx]);
                        }
                }
            }
        }
    }

    const float* rz = g_rg + z * SH * SW;
    const int dys[4] = {0, 1, 1, 1};
    const int dxs[4] = {1, 1, 0, -1};
    float num = 0.0f, den = 0.0f;
    #pragma unroll
    for (int p = 0; p < 4; p++) {
        int py = p >> 1, px = p & 1;
        int gy = blockIdx.y*8  + qy + py;
        int gx = blockIdx.x*32 + qx + px;
        float ds[4];
        unpack2(acc[0][p], ds[0], ds[1]);
        unpack2(acc[1][p], ds[2], ds[3]);
        #pragma unroll
        for (int g = 0; g < 4; g++) ds[g] += bp[g];

        float rv = rz[gy*SW + gx];
        float lc = logf(rv + 1e-6f);
        bool  mc = rv > 0.1f;
        #pragma unroll
        for (int g = 0; g < 4; g++) {
            int ny = gy + dys[g], nx = gx + dxs[g];
            bool inb = (ny < SH) && (nx >= 0) && (nx < SW);
            float nv = inb ? rz[ny*SW + nx] : 0.0f;
            float gg = lc - logf(nv + 1e-6f);
            float mk = (mc && (nv > 0.1f)) ? 1.0f : 0.0f;
            float a  = fabsf(ds[g] - gg);
            float sl1 = (a < 0.01f) ? (0.5f * a * a / 0.01f) : (a - 0.005f);
            num += sl1 * mk;
            den += mk;
        }
    }
    rnum[tid] = num; rden[tid] = den;
    __syncthreads();
    for (int s = 32; s > 0; s >>= 1) {
        if (tid < s) { rnum[tid] += rnum[tid+s]; rden[tid] += rden[tid+s]; }
        __syncthreads();
    }
    if (tid == 0) {
        int it = z >> 2;
        atomicAdd(&g_num[it], rnum[0]);
        atomicAdd(&g_den[it], rden[0]);
    }
}

// ---------------- finalize: mean over iterations of num/den ----------------
__global__ void finalize_kernel(float* out) {
    if (threadIdx.x == 0 && blockIdx.x == 0) {
        float s = 0.0f;
        for (int i = 0; i < IT; i++) s += g_num[i] / g_den[i];
        out[0] = s / (float)IT;
    }
}

// ---------------- launch ----------------
extern "C" void kernel_launch(void* const* d_in, const int* in_sizes, int n_in,
                              void* d_out, int out_size) {
    const float* x    = (const float*)d_in[0];
    const float* d    = (const float*)d_in[1];
    const float* gts  = (const float*)d_in[2];
    const float* rnd  = (const float*)d_in[3];
    const float* Watt = (const float*)d_in[4];
    const float* batt = (const float*)d_in[5];
    const float* Wp   = (const float*)d_in[6];
    const float* bp   = (const float*)d_in[7];
    float* out = (float*)d_out;

    float *xt, *dt;
    cudaGetSymbolAddress((void**)&xt, g_xt);
    cudaGetSymbolAddress((void**)&dt, g_dt);

    zero_kernel<<<1, 32>>>();
    transpose_kernel<<<dim3(GH*GW/32, NB), dim3(32, 8)>>>(x, xt, GH*GW);
    transpose_kernel<<<dim3(SH*SW/32, NB), dim3(32, 8)>>>(d, dt, SH*SW);
    pool_kernel<<<(IT*NB*SH*SW + 255)/256, 256>>>(gts, rnd);
    sample_kernel<<<(IT*NB*SH*SW*32)/256, 256>>>();
    conv_att_kernel<<<dim3(SW/32, SH/8, IT*NB), 128>>>(Watt, batt);
    conv_post_loss_kernel<<<dim3(SW/32, SH/8, IT*NB), 64>>>(Wp, bp);
    finalize_kernel<<<1, 32>>>(out);
}

// round 10
// speedup vs baseline: 2.3736x; 1.5290x over previous
#include <cuda_runtime.h>
#include <cuda_bf16.h>
#include <math.h>
#include <cstdint>

#define IT 20
#define NB 4
#define GH 480
#define GW 640
#define SH 120
#define SW 160
#define NC 32

typedef unsigned long long u64;

// ---------------- static device scratch (no runtime allocation) ----------------
__device__ float    g_xt[NB*GH*GW*NC];              // x transposed to NHWC  (157 MB)
__device__ float    g_dt[NB*SH*SW*NC];              // d transposed to NHWC  (9.8 MB)
__device__ float    g_rg[IT*NB*SH*SW];              // pooled gt
__device__ float    g_ixb[IT*NB*SH*SW];             // sample x pixel coord
__device__ float    g_iyb[IT*NB*SH*SW];             // sample y pixel coord
__device__ uint32_t g_feat[IT*NB*SH*SW*16];         // sampled features NHWC bf16x2 (98 MB)
__device__ float    g_attd[IT*NB*SH*SW*NC];         // sigmoid(conv)*d NHWC f32     (196 MB)
__device__ float    g_num[IT];
__device__ float    g_den[IT];

// ---------------- helpers ----------------
__device__ __forceinline__ u64 pack2(float v) {
    u64 r; asm("mov.b64 %0, {%1, %1};" : "=l"(r) : "f"(v)); return r;
}
__device__ __forceinline__ void fma2(u64& acc, u64 a, u64 b) {
    asm("fma.rn.f32x2 %0, %1, %2, %0;" : "+l"(acc) : "l"(a), "l"(b));
}
__device__ __forceinline__ void unpack2(u64 v, float& lo, float& hi) {
    asm("mov.b64 {%0, %1}, %2;" : "=f"(lo), "=f"(hi) : "l"(v));
}
__device__ __forceinline__ uint32_t pack_bf16(float lo, float hi) {
    uint32_t r;
    asm("cvt.rn.bf16x2.f32 %0, %1, %2;" : "=r"(r) : "f"(hi), "f"(lo));
    return r;
}
__device__ __forceinline__ uint32_t smem_to_u32(const void* p) {
    uint32_t a;
    asm("{ .reg .u64 t; cvta.to.shared.u64 t, %1; cvt.u32.u64 %0, t; }" : "=r"(a) : "l"(p));
    return a;
}
__device__ __forceinline__ void ldmatrix_x4(uint32_t* r, uint32_t addr) {
    asm volatile("ldmatrix.sync.aligned.m8n8.x4.shared.b16 {%0, %1, %2, %3}, [%4];"
        : "=r"(r[0]), "=r"(r[1]), "=r"(r[2]), "=r"(r[3]) : "r"(addr));
}
__device__ __forceinline__ void mma_bf16(float* c, const uint32_t* a, const uint32_t* b) {
    asm volatile("mma.sync.aligned.m16n8k16.row.col.f32.bf16.bf16.f32 "
        "{%0, %1, %2, %3}, {%4, %5, %6, %7}, {%8, %9}, {%0, %1, %2, %3};"
        : "+f"(c[0]), "+f"(c[1]), "+f"(c[2]), "+f"(c[3])
        : "r"(a[0]), "r"(a[1]), "r"(a[2]), "r"(a[3]), "r"(b[0]), "r"(b[1]));
}

// ---------------- zero per-iteration accumulators ----------------
__global__ void zero_kernel() {
    int t = threadIdx.x;
    if (t < IT) { g_num[t] = 0.0f; g_den[t] = 0.0f; }
}

// ---------------- NCHW -> NHWC transpose (C=32), per batch ----------------
__global__ void transpose_kernel(const float* __restrict__ src, float* __restrict__ dst, int S) {
    __shared__ float t[32][33];
    int s0 = blockIdx.x * 32;
    const float* sb = src + (size_t)blockIdx.y * NC * S;
    float*       db = dst + (size_t)blockIdx.y * S * NC;
    int lx = threadIdx.x, ly = threadIdx.y;
    #pragma unroll
    for (int cc = 0; cc < 4; cc++) {
        int c = ly + cc * 8;
        t[c][lx] = sb[(size_t)c * S + s0 + lx];
    }
    __syncthreads();
    #pragma unroll
    for (int cc = 0; cc < 4; cc++) {
        int sr = ly + cc * 8;
        db[(size_t)(s0 + sr) * NC + lx] = t[lx][sr];
    }
}

// ---------------- random pooling + sample-coordinate computation ----------------
__global__ void pool_kernel(const float* __restrict__ gts, const float* __restrict__ rnd) {
    int tid = blockIdx.x * blockDim.x + threadIdx.x;
    if (tid >= IT*NB*SH*SW) return;
    int x  = tid % SW;  int t1 = tid / SW;
    int y  = t1 % SH;   int t2 = t1 / SH;
    int b  = t2 % NB;   int it = t2 / NB;
    const float* gp = gts + b * GH * GW;
    const float* rp = rnd + (it * NB + b) * GH * GW;

    float best = -1.0f;
    int srow = y*4, scol = x*4;
    #pragma unroll
    for (int bi = 0; bi < 4; bi++) {
        int row = y*4 + bi;
        #pragma unroll
        for (int bj = 0; bj < 4; bj++) {
            int col = x*4 + bj;
            float g  = gp[row*GW + col];
            float rm = (g > 0.1f) ? rp[row*GW + col] : 0.0f;
            if (rm > best) { best = rm; srow = row; scol = col; }
        }
    }
    float rv = gp[srow*GW + scol];
    if (rv < 0.1f) rv = 0.0f;
    g_rg[tid] = rv;

    int index = srow*GW + scol + 1282;   // bias = 2 + 2*640
    float fx = (float)(index % GW);
    float fy = (float)(index / GW);
    float gx = 2.0f * (fx / (float)GW - 0.5f);
    float gy = 2.0f * (fy / (float)GH - 0.5f);
    g_ixb[tid] = (gx + 1.0f) * 0.5f * (float)(GW - 1);
    g_iyb[tid] = (gy + 1.0f) * 0.5f * (float)(GH - 1);
}

// ---------------- bilinear grid-sample: one warp per point, lane = channel; bf16 output ----------------
__global__ void sample_kernel() {
    int gt  = blockIdx.x * blockDim.x + threadIdx.x;
    int pid = gt >> 5;
    int lane = gt & 31;
    if (pid >= IT*NB*SH*SW) return;
    float ix = g_ixb[pid], iy = g_iyb[pid];
    float x0f = floorf(ix), y0f = floorf(iy);
    float wx = ix - x0f, wy = iy - y0f;
    int x0 = (int)x0f, y0 = (int)y0f;
    int b = (pid / (SH*SW)) % NB;
    const float* xb = g_xt + b * GH * GW * NC;
    float acc = 0.0f;
#define CORNER(XC, YC, WG) {                                            \
        int xc = (XC), yc = (YC);                                       \
        bool v = (xc >= 0) && (xc <= GW-1) && (yc >= 0) && (yc <= GH-1);\
        int xi = min(max(xc, 0), GW-1);                                 \
        int yi = min(max(yc, 0), GH-1);                                 \
        float val = xb[(yi*GW + xi)*NC + lane];                         \
        acc += val * (v ? (WG) : 0.0f);                                 \
    }
    CORNER(x0,   y0,   (1.0f-wx)*(1.0f-wy));
    CORNER(x0+1, y0,   wx*(1.0f-wy));
    CORNER(x0,   y0+1, (1.0f-wx)*wy);
    CORNER(x0+1, y0+1, wx*wy);
#undef CORNER
    float hi = __shfl_down_sync(0xffffffffu, acc, 1);
    if ((lane & 1) == 0)
        g_feat[pid*16 + (lane >> 1)] = pack_bf16(acc, hi);
}

// ---------------- conv3x3 (32->32) via HMMA (mma.sync bf16) + sigmoid*d -> attd (f32) ----------------
// block tile = 8 rows x 32 px (256 px). 4 warps; warp w owns co-tile [w*8, w*8+8).
// M = 256 px (16 m16-tiles), N = 8/warp, K = 288 (9 taps x 32 ci = 18 k16-steps).
#define PXS 80                                     // pixel record stride in bytes (32 bf16 + pad)
__global__ __launch_bounds__(128) void conv_att_kernel(const float* __restrict__ Watt,
                                                       const float* __restrict__ batt) {
    __shared__ __align__(16) char s_tile[10*34*PXS];          // 27200 B, im2col window
    __shared__ __align__(16) __nv_bfloat16 s_w[32][296];      // k-major weights, 18944 B

    int tid = threadIdx.x;
    int wid = tid >> 5, lane = tid & 31;
    int bx = blockIdx.x, by = blockIdx.y, z = blockIdx.z;

    // ---- load feat window (10 x 34 px x 16 bf16x2 words) ----
    const uint32_t* fz = g_feat + (size_t)z * SH * SW * 16;
    int gy0 = by*8 - 1, gx0 = bx*32 - 1;
    for (int idx = tid; idx < 10*34*16; idx += 128) {
        int w = idx & 15; int rem = idx >> 4;
        int xx = rem % 34; int yy = rem / 34;
        int ggy = gy0 + yy, ggx = gx0 + xx;
        uint32_t v = 0;
        if (ggy >= 0 && ggy < SH && ggx >= 0 && ggx < SW)
            v = fz[(ggy*SW + ggx)*16 + w];
        *(uint32_t*)(s_tile + (yy*34 + xx)*PXS + w*4) = v;
    }
    // ---- weights: Watt[co][ci][tap] -> s_w[co][k], k = tap*32+ci ----
    for (int idx = tid; idx < 32*288; idx += 128) {
        int co = idx / 288; int k = idx - co*288;
        int tap = k >> 5, ci = k & 31;
        s_w[co][k] = __float2bfloat16(Watt[(co*32 + ci)*9 + tap]);
    }
    __syncthreads();

    int g  = lane >> 2, t2 = lane & 3;
    // ---- B fragments: 18 k-steps x 2 regs, held in registers ----
    uint32_t bf[18][2];
    #pragma unroll
    for (int j = 0; j < 18; j++) {
        int k0 = j*16 + t2*2;
        bf[j][0] = *(const uint32_t*)&s_w[wid*8 + g][k0];
        bf[j][1] = *(const uint32_t*)&s_w[wid*8 + g][k0 + 8];
    }

    // ldmatrix per-thread row geometry
    int m_row = (lane & 7) + ((lane & 8) ? 8 : 0);
    uint32_t k8 = (lane & 16) ? 16u : 0u;             // bytes
    uint32_t tb = smem_to_u32(s_tile);
    int b = z & 3;
    int co0 = wid*8 + t2*2;
    float bt0 = batt[co0], bt1 = batt[co0+1];

    // ---- 8 m-tile pairs ----
    #pragma unroll 1
    for (int mp = 0; mp < 8; mp++) {
        int p0 = mp*32 + m_row;
        int p1 = p0 + 16;
        uint32_t a0base = tb + (uint32_t)(((p0 >> 5)*34 + (p0 & 31))*PXS) + k8;
        uint32_t a1base = tb + (uint32_t)(((p1 >> 5)*34 + (p1 & 31))*PXS) + k8;

        float acc0[4] = {0,0,0,0};
        float acc1[4] = {0,0,0,0};
        #pragma unroll
        for (int t = 0; t < 9; t++) {
            uint32_t toff = (uint32_t)(((t/3)*34 + (t%3))*PXS);
            #pragma unroll
            for (int h = 0; h < 2; h++) {
                int j = t*2 + h;
                uint32_t A0[4], A1[4];
                ldmatrix_x4(A0, a0base + toff + h*32);
                ldmatrix_x4(A1, a1base + toff + h*32);
                mma_bf16(acc0, A0, bf[j]);
                mma_bf16(acc1, A1, bf[j]);
            }
        }

        // ---- epilogue: bias + sigmoid + *d -> g_attd (f32) ----
        #pragma unroll
        for (int half = 0; half < 2; half++) {
            float* acc = half ? acc1 : acc0;
            int pb = mp*32 + half*16;
            #pragma unroll
            for (int r = 0; r < 2; r++) {
                int p = pb + g + r*8;
                int gy = by*8 + (p >> 5);
                int gx = bx*32 + (p & 31);
                float2 dv = *(const float2*)&g_dt[((size_t)(b*SH + gy)*SW + gx)*NC + co0];
                float v0 = acc[r*2+0] + bt0;
                float v1 = acc[r*2+1] + bt1;
                float a0 = dv.x / (1.0f + __expf(-v0));
                float a1 = dv.y / (1.0f + __expf(-v1));
                float2 o = make_float2(a0, a1);
                *(float2*)&g_attd[((size_t)z*SH*SW + gy*SW + gx)*NC + co0] = o;
            }
        }
    }
}

// ---------------- conv3x3 (32->4, f32 attd) + log-grads + masked smooth-L1 + reduction ----------------
__global__ __launch_bounds__(64) void conv_post_loss_kernel(const float* __restrict__ Wp,
                                                            const float* __restrict__ bp) {
    __shared__ float s_tile[10][8][35];
    __shared__ __align__(16) float s_w[9][8][4];
    __shared__ float rnum[64];
    __shared__ float rden[64];
    int tid = threadIdx.x;
    int qx  = (tid & 15) * 2;
    int qy  = (tid >> 4) * 2;
    int z   = blockIdx.z;
    int gx0 = blockIdx.x * 32 - 1;
    int gy0 = blockIdx.y * 8  - 1;
    const float* az = g_attd + (size_t)z * SH * SW * NC;

    u64 acc[2][4];
    #pragma unroll
    for (int i = 0; i < 2; i++)
        #pragma unroll
        for (int p = 0; p < 4; p++) acc[i][p] = 0ULL;

    for (int cc = 0; cc < 4; cc++) {
        __syncthreads();
        for (int idx = tid; idx < 10*34*8; idx += 64) {
            int ci = idx & 7; int rem = idx >> 3;
            int xx = rem % 34; int yy = rem / 34;
            int ggy = gy0 + yy, ggx = gx0 + xx;
            float v = 0.0f;
            if (ggy >= 0 && ggy < SH && ggx >= 0 && ggx < SW)
                v = az[(ggy*SW + ggx)*NC + cc*8 + ci];
            s_tile[yy][ci][xx] = v;
        }
        for (int idx = tid; idx < 9*8*4; idx += 64) {
            int g = idx & 3; int rem = idx >> 2;
            int ci = rem & 7; int k = rem >> 3;
            s_w[k][ci][g] = Wp[(g*32 + cc*8 + ci)*9 + k];
        }
        __syncthreads();

        #pragma unroll 2
        for (int ci = 0; ci < 8; ci++) {
            u64 t2[4][4];
            #pragma unroll
            for (int i = 0; i < 4; i++)
                #pragma unroll
                for (int j = 0; j < 4; j++)
                    t2[i][j] = pack2(s_tile[qy + i][ci][qx + j]);
            #pragma unroll
            for (int ky = 0; ky < 3; ky++) {
                #pragma unroll
                for (int kx = 0; kx < 3; kx++) {
                    int k = ky*3 + kx;
                    ulonglong2 wv = *(const ulonglong2*)&s_w[k][ci][0];
                    #pragma unroll
                    for (int py = 0; py < 2; py++)
                        #pragma unroll
                        for (int px = 0; px < 2; px++) {
                            fma2(acc[0][py*2 + px], wv.x, t2[py + ky][px + kx]);
                            fma2(acc[1][py*2 + px], wv.y, t2[py + ky][px + kx]);
                        }
                }
            }
        }
    }

    const float* rz = g_rg + z * SH * SW;
    const int dys[4] = {0, 1, 1, 1};
    const int dxs[4] = {1, 1, 0, -1};
    float num = 0.0f, den = 0.0f;
    #pragma unroll
    for (int p = 0; p < 4; p++) {
        int py = p >> 1, px = p & 1;
        int gy = blockIdx.y*8  + qy + py;
        int gx = blockIdx.x*32 + qx + px;
        float ds[4];
        unpack2(acc[0][p], ds[0], ds[1]);
        unpack2(acc[1][p], ds[2], ds[3]);
        #pragma unroll
        for (int g = 0; g < 4; g++) ds[g] += bp[g];

        float rv = rz[gy*SW + gx];
        float lc = logf(rv + 1e-6f);
        bool  mc = rv > 0.1f;
        #pragma unroll
        for (int g = 0; g < 4; g++) {
            int ny = gy + dys[g], nx = gx + dxs[g];
            bool inb = (ny < SH) && (nx >= 0) && (nx < SW);
            float nv = inb ? rz[ny*SW + nx] : 0.0f;
            float gg = lc - logf(nv + 1e-6f);
            float mk = (mc && (nv > 0.1f)) ? 1.0f : 0.0f;
            float a  = fabsf(ds[g] - gg);
            float sl1 = (a < 0.01f) ? (0.5f * a * a / 0.01f) : (a - 0.005f);
            num += sl1 * mk;
            den += mk;
        }
    }
    rnum[tid] = num; rden[tid] = den;
    __syncthreads();
    for (int s = 32; s > 0; s >>= 1) {
        if (tid < s) { rnum[tid] += rnum[tid+s]; rden[tid] += rden[tid+s]; }
        __syncthreads();
    }
    if (tid == 0) {
        int it = z >> 2;
        atomicAdd(&g_num[it], rnum[0]);
        atomicAdd(&g_den[it], rden[0]);
    }
}

// ---------------- finalize: mean over iterations of num/den ----------------
__global__ void finalize_kernel(float* out) {
    if (threadIdx.x == 0 && blockIdx.x == 0) {
        float s = 0.0f;
        for (int i = 0; i < IT; i++) s += g_num[i] / g_den[i];
        out[0] = s / (float)IT;
    }
}

// ---------------- launch ----------------
extern "C" void kernel_launch(void* const* d_in, const int* in_sizes, int n_in,
                              void* d_out, int out_size) {
    const float* x    = (const float*)d_in[0];
    const float* d    = (const float*)d_in[1];
    const float* gts  = (const float*)d_in[2];
    const float* rnd  = (const float*)d_in[3];
    const float* Watt = (const float*)d_in[4];
    const float* batt = (const float*)d_in[5];
    const float* Wp   = (const float*)d_in[6];
    const float* bp   = (const float*)d_in[7];
    float* out = (float*)d_out;

    float *xt, *dt;
    cudaGetSymbolAddress((void**)&xt, g_xt);
    cudaGetSymbolAddress((void**)&dt, g_dt);

    zero_kernel<<<1, 32>>>();
    transpose_kernel<<<dim3(GH*GW/32, NB), dim3(32, 8)>>>(x, xt, GH*GW);
    transpose_kernel<<<dim3(SH*SW/32, NB), dim3(32, 8)>>>(d, dt, SH*SW);
    pool_kernel<<<(IT*NB*SH*SW + 255)/256, 256>>>(gts, rnd);
    sample_kernel<<<(IT*NB*SH*SW*32)/256, 256>>>();
    conv_att_kernel<<<dim3(SW/32, SH/8, IT*NB), 128>>>(Watt, batt);
    conv_post_loss_kernel<<<dim3(SW/32, SH/8, IT*NB), 64>>>(Wp, bp);
    finalize_kernel<<<1, 32>>>(out);
}

// round 12
// speedup vs baseline: 2.5223x; 1.0626x over previous
#include <cuda_runtime.h>
#include <cuda_bf16.h>
#include <math.h>
#include <cstdint>

#define IT 20
#define NB 4
#define GH 480
#define GW 640
#define SH 120
#define SW 160
#define NC 32

typedef unsigned long long u64;

// ---------------- static device scratch (no runtime allocation) ----------------
__device__ float    g_xt[NB*GH*GW*NC];              // x transposed to NHWC  (157 MB)
__device__ float    g_dt[NB*SH*SW*NC];              // d transposed to NHWC  (9.8 MB)
__device__ float    g_rg[IT*NB*SH*SW];              // pooled gt
__device__ float    g_ixb[IT*NB*SH*SW];             // sample x pixel coord
__device__ float    g_iyb[IT*NB*SH*SW];             // sample y pixel coord
__device__ uint32_t g_feat[IT*NB*SH*SW*16];         // sampled features NHWC bf16x2 (98 MB)
__device__ uint32_t g_attd[IT*NB*SH*SW*16];         // sigmoid(conv)*d NHWC bf16x2  (98 MB)
__device__ float    g_num[IT];
__device__ float    g_den[IT];

// ---------------- helpers ----------------
__device__ __forceinline__ uint32_t pack_bf16(float lo, float hi) {
    uint32_t r;
    asm("cvt.rn.bf16x2.f32 %0, %1, %2;" : "=r"(r) : "f"(hi), "f"(lo));
    return r;
}
__device__ __forceinline__ uint32_t smem_to_u32(const void* p) {
    uint32_t a;
    asm("{ .reg .u64 t; cvta.to.shared.u64 t, %1; cvt.u32.u64 %0, t; }" : "=r"(a) : "l"(p));
    return a;
}
__device__ __forceinline__ void ldmatrix_x4(uint32_t* r, uint32_t addr) {
    asm volatile("ldmatrix.sync.aligned.m8n8.x4.shared.b16 {%0, %1, %2, %3}, [%4];"
        : "=r"(r[0]), "=r"(r[1]), "=r"(r[2]), "=r"(r[3]) : "r"(addr));
}
__device__ __forceinline__ void mma_bf16(float* c, const uint32_t* a, const uint32_t* b) {
    asm volatile("mma.sync.aligned.m16n8k16.row.col.f32.bf16.bf16.f32 "
        "{%0, %1, %2, %3}, {%4, %5, %6, %7}, {%8, %9}, {%0, %1, %2, %3};"
        : "+f"(c[0]), "+f"(c[1]), "+f"(c[2]), "+f"(c[3])
        : "r"(a[0]), "r"(a[1]), "r"(a[2]), "r"(a[3]), "r"(b[0]), "r"(b[1]));
}

// ---------------- zero per-iteration accumulators ----------------
__global__ void zero_kernel() {
    int t = threadIdx.x;
    if (t < IT) { g_num[t] = 0.0f; g_den[t] = 0.0f; }
}

// ---------------- NCHW -> NHWC transpose (C=32), per batch ----------------
__global__ void transpose_kernel(const float* __restrict__ src, float* __restrict__ dst, int S) {
    __shared__ float t[32][33];
    int s0 = blockIdx.x * 32;
    const float* sb = src + (size_t)blockIdx.y * NC * S;
    float*       db = dst + (size_t)blockIdx.y * S * NC;
    int lx = threadIdx.x, ly = threadIdx.y;
    #pragma unroll
    for (int cc = 0; cc < 4; cc++) {
        int c = ly + cc * 8;
        t[c][lx] = sb[(size_t)c * S + s0 + lx];
    }
    __syncthreads();
    #pragma unroll
    for (int cc = 0; cc < 4; cc++) {
        int sr = ly + cc * 8;
        db[(size_t)(s0 + sr) * NC + lx] = t[lx][sr];
    }
}

// ---------------- random pooling + sample-coordinate computation ----------------
__global__ void pool_kernel(const float* __restrict__ gts, const float* __restrict__ rnd) {
    int tid = blockIdx.x * blockDim.x + threadIdx.x;
    if (tid >= IT*NB*SH*SW) return;
    int x  = tid % SW;  int t1 = tid / SW;
    int y  = t1 % SH;   int t2 = t1 / SH;
    int b  = t2 % NB;   int it = t2 / NB;
    const float* gp = gts + b * GH * GW;
    const float* rp = rnd + (it * NB + b) * GH * GW;

    float best = -1.0f;
    int srow = y*4, scol = x*4;
    #pragma unroll
    for (int bi = 0; bi < 4; bi++) {
        int row = y*4 + bi;
        #pragma unroll
        for (int bj = 0; bj < 4; bj++) {
            int col = x*4 + bj;
            float g  = gp[row*GW + col];
            float rm = (g > 0.1f) ? rp[row*GW + col] : 0.0f;
            if (rm > best) { best = rm; srow = row; scol = col; }
        }
    }
    float rv = gp[srow*GW + scol];
    if (rv < 0.1f) rv = 0.0f;
    g_rg[tid] = rv;

    int index = srow*GW + scol + 1282;   // bias = 2 + 2*640
    float fx = (float)(index % GW);
    float fy = (float)(index / GW);
    float gx = 2.0f * (fx / (float)GW - 0.5f);
    float gy = 2.0f * (fy / (float)GH - 0.5f);
    g_ixb[tid] = (gx + 1.0f) * 0.5f * (float)(GW - 1);
    g_iyb[tid] = (gy + 1.0f) * 0.5f * (float)(GH - 1);
}

// ---------------- bilinear grid-sample: one warp per point, lane = channel; bf16 output ----------------
__global__ void sample_kernel() {
    int gt  = blockIdx.x * blockDim.x + threadIdx.x;
    int pid = gt >> 5;
    int lane = gt & 31;
    if (pid >= IT*NB*SH*SW) return;
    float ix = g_ixb[pid], iy = g_iyb[pid];
    float x0f = floorf(ix), y0f = floorf(iy);
    float wx = ix - x0f, wy = iy - y0f;
    int x0 = (int)x0f, y0 = (int)y0f;
    int b = (pid / (SH*SW)) % NB;
    const float* xb = g_xt + b * GH * GW * NC;
    float acc = 0.0f;
#define CORNER(XC, YC, WG) {                                            \
        int xc = (XC), yc = (YC);                                       \
        bool v = (xc >= 0) && (xc <= GW-1) && (yc >= 0) && (yc <= GH-1);\
        int xi = min(max(xc, 0), GW-1);                                 \
        int yi = min(max(yc, 0), GH-1);                                 \
        float val = xb[(yi*GW + xi)*NC + lane];                         \
        acc += val * (v ? (WG) : 0.0f);                                 \
    }
    CORNER(x0,   y0,   (1.0f-wx)*(1.0f-wy));
    CORNER(x0+1, y0,   wx*(1.0f-wy));
    CORNER(x0,   y0+1, (1.0f-wx)*wy);
    CORNER(x0+1, y0+1, wx*wy);
#undef CORNER
    float hi = __shfl_down_sync(0xffffffffu, acc, 1);
    if ((lane & 1) == 0)
        g_feat[pid*16 + (lane >> 1)] = pack_bf16(acc, hi);
}

// ---------------- conv3x3 (32->32) via HMMA + sigmoid*d -> attd (bf16) ----------------
// block tile = 8 rows x 32 px (256 px). 4 warps; warp w owns co-tile [w*8, w*8+8).
#define PXS 80                                     // pixel record stride in bytes (32 bf16 + pad)
__global__ __launch_bounds__(128) void conv_att_kernel(const float* __restrict__ Watt,
                                                       const float* __restrict__ batt) {
    __shared__ __align__(16) char s_tile[10*34*PXS];          // 27200 B, im2col window
    __shared__ __align__(16) __nv_bfloat16 s_w[32][296];      // k-major weights

    int tid = threadIdx.x;
    int wid = tid >> 5, lane = tid & 31;
    int bx = blockIdx.x, by = blockIdx.y, z = blockIdx.z;

    // ---- load feat window (10 x 34 px x 16 bf16x2 words) ----
    const uint32_t* fz = g_feat + (size_t)z * SH * SW * 16;
    int gy0 = by*8 - 1, gx0 = bx*32 - 1;
    for (int idx = tid; idx < 10*34*16; idx += 128) {
        int w = idx & 15; int rem = idx >> 4;
        int xx = rem % 34; int yy = rem / 34;
        int ggy = gy0 + yy, ggx = gx0 + xx;
        uint32_t v = 0;
        if (ggy >= 0 && ggy < SH && ggx >= 0 && ggx < SW)
            v = fz[(ggy*SW + ggx)*16 + w];
        *(uint32_t*)(s_tile + (yy*34 + xx)*PXS + w*4) = v;
    }
    // ---- weights: Watt[co][ci][tap] -> s_w[co][k], k = tap*32+ci ----
    for (int idx = tid; idx < 32*288; idx += 128) {
        int co = idx / 288; int k = idx - co*288;
        int tap = k >> 5, ci = k & 31;
        s_w[co][k] = __float2bfloat16(Watt[(co*32 + ci)*9 + tap]);
    }
    __syncthreads();

    int g  = lane >> 2, t2 = lane & 3;
    uint32_t bf[18][2];
    #pragma unroll
    for (int j = 0; j < 18; j++) {
        int k0 = j*16 + t2*2;
        bf[j][0] = *(const uint32_t*)&s_w[wid*8 + g][k0];
        bf[j][1] = *(const uint32_t*)&s_w[wid*8 + g][k0 + 8];
    }

    int m_row = (lane & 7) + ((lane & 8) ? 8 : 0);
    uint32_t k8 = (lane & 16) ? 16u : 0u;
    uint32_t tb = smem_to_u32(s_tile);
    int b = z & 3;
    int co0 = wid*8 + t2*2;
    float bt0 = batt[co0], bt1 = batt[co0+1];

    #pragma unroll 1
    for (int mp = 0; mp < 8; mp++) {
        int p0 = mp*32 + m_row;
        int p1 = p0 + 16;
        uint32_t a0base = tb + (uint32_t)(((p0 >> 5)*34 + (p0 & 31))*PXS) + k8;
        uint32_t a1base = tb + (uint32_t)(((p1 >> 5)*34 + (p1 & 31))*PXS) + k8;

        float acc0[4] = {0,0,0,0};
        float acc1[4] = {0,0,0,0};
        #pragma unroll
        for (int t = 0; t < 9; t++) {
            uint32_t toff = (uint32_t)(((t/3)*34 + (t%3))*PXS);
            #pragma unroll
            for (int h = 0; h < 2; h++) {
                int j = t*2 + h;
                uint32_t A0[4], A1[4];
                ldmatrix_x4(A0, a0base + toff + h*32);
                ldmatrix_x4(A1, a1base + toff + h*32);
                mma_bf16(acc0, A0, bf[j]);
                mma_bf16(acc1, A1, bf[j]);
            }
        }

        // ---- epilogue: bias + sigmoid + *d -> g_attd (bf16x2) ----
        #pragma unroll
        for (int half = 0; half < 2; half++) {
            float* acc = half ? acc1 : acc0;
            int pb = mp*32 + half*16;
            #pragma unroll
            for (int r = 0; r < 2; r++) {
                int p = pb + g + r*8;
                int gy = by*8 + (p >> 5);
                int gx = bx*32 + (p & 31);
                float2 dv = *(const float2*)&g_dt[((size_t)(b*SH + gy)*SW + gx)*NC + co0];
                float v0 = acc[r*2+0] + bt0;
                float v1 = acc[r*2+1] + bt1;
                float a0 = dv.x / (1.0f + __expf(-v0));
                float a1 = dv.y / (1.0f + __expf(-v1));
                g_attd[((size_t)z*SH*SW + gy*SW + gx)*16 + (co0 >> 1)] = pack_bf16(a0, a1);
            }
        }
    }
}

// ---------------- conv3x3 (32->4) via HMMA + log-grads + masked smooth-L1 + reduction ----------------
// same tile geometry as conv_att; N=8 with co 4..7 zero-padded; warp w owns m-tiles [w*4, w*4+4).
__global__ __launch_bounds__(128) void conv_post_loss_kernel(const float* __restrict__ Wp,
                                                             const float* __restrict__ bp) {
    __shared__ __align__(16) char s_tile[10*34*PXS];
    __shared__ __align__(16) __nv_bfloat16 s_wp[8][296];
    __shared__ float s_ds[256][4];
    __shared__ float rnum[128];
    __shared__ float rden[128];

    int tid = threadIdx.x;
    int wid = tid >> 5, lane = tid & 31;
    int bx = blockIdx.x, by = blockIdx.y, z = blockIdx.z;

    // ---- load attd window (10 x 34 px x 16 bf16x2 words) ----
    const uint32_t* az = g_attd + (size_t)z * SH * SW * 16;
    int gy0 = by*8 - 1, gx0 = bx*32 - 1;
    for (int idx = tid; idx < 10*34*16; idx += 128) {
        int w = idx & 15; int rem = idx >> 4;
        int xx = rem % 34; int yy = rem / 34;
        int ggy = gy0 + yy, ggx = gx0 + xx;
        uint32_t v = 0;
        if (ggy >= 0 && ggy < SH && ggx >= 0 && ggx < SW)
            v = az[(ggy*SW + ggx)*16 + w];
        *(uint32_t*)(s_tile + (yy*34 + xx)*PXS + w*4) = v;
    }
    // ---- weights: Wp[co][ci][tap] -> s_wp[co][k]; rows 4..7 zero ----
    for (int idx = tid; idx < 8*288; idx += 128) {
        int co = idx / 288; int k = idx - co*288;
        int tap = k >> 5, ci = k & 31;
        s_wp[co][k] = (co < 4) ? __float2bfloat16(Wp[(co*32 + ci)*9 + tap])
                               : __float2bfloat16(0.0f);
    }
    __syncthreads();

    int g  = lane >> 2, t2 = lane & 3;
    uint32_t bf[18][2];
    #pragma unroll
    for (int j = 0; j < 18; j++) {
        int k0 = j*16 + t2*2;
        bf[j][0] = *(const uint32_t*)&s_wp[g][k0];
        bf[j][1] = *(const uint32_t*)&s_wp[g][k0 + 8];
    }

    int m_row = (lane & 7) + ((lane & 8) ? 8 : 0);
    uint32_t k8 = (lane & 16) ? 16u : 0u;
    uint32_t tb = smem_to_u32(s_tile);

    #pragma unroll 1
    for (int q = 0; q < 4; q++) {
        int mt = wid*4 + q;
        int p0 = mt*16 + m_row;
        uint32_t abase = tb + (uint32_t)(((p0 >> 5)*34 + (p0 & 31))*PXS) + k8;

        float acc[4] = {0,0,0,0};
        #pragma unroll
        for (int t = 0; t < 9; t++) {
            uint32_t toff = (uint32_t)(((t/3)*34 + (t%3))*PXS);
            #pragma unroll
            for (int h = 0; h < 2; h++) {
                uint32_t A[4];
                ldmatrix_x4(A, abase + toff + h*32);
                mma_bf16(acc, A, bf[t*2 + h]);
            }
        }
        // D fragment: rows g, g+8 of tile; cols t2*2, t2*2+1 (valid for t2<2)
        if (t2 < 2) {
            int pA = mt*16 + g;
            int pB = pA + 8;
            s_ds[pA][t2*2+0] = acc[0];
            s_ds[pA][t2*2+1] = acc[1];
            s_ds[pB][t2*2+0] = acc[2];
            s_ds[pB][t2*2+1] = acc[3];
        }
    }
    __syncthreads();

    // ---- loss phase: 2 pixels per thread ----
    const float* rz = g_rg + z * SH * SW;
    const int dys[4] = {0, 1, 1, 1};
    const int dxs[4] = {1, 1, 0, -1};
    float num = 0.0f, den = 0.0f;
    #pragma unroll
    for (int pp = 0; pp < 2; pp++) {
        int p = tid + pp*128;
        int gy = by*8 + (p >> 5);
        int gx = bx*32 + (p & 31);
        float4 dsv = *(const float4*)&s_ds[p][0];
        float ds[4] = {dsv.x + bp[0], dsv.y + bp[1], dsv.z + bp[2], dsv.w + bp[3]};

        float rv = rz[gy*SW + gx];
        float lc = logf(rv + 1e-6f);
        bool  mc = rv > 0.1f;
        #pragma unroll
        for (int gI = 0; gI < 4; gI++) {
            int ny = gy + dys[gI], nx = gx + dxs[gI];
            bool inb = (ny < SH) && (nx >= 0) && (nx < SW);
            float nv = inb ? rz[ny*SW + nx] : 0.0f;
            float gg = lc - logf(nv + 1e-6f);
            float mk = (mc && (nv > 0.1f)) ? 1.0f : 0.0f;
            float a  = fabsf(ds[gI] - gg);
            float sl1 = (a < 0.01f) ? (0.5f * a * a / 0.01f) : (a - 0.005f);
            num += sl1 * mk;
            den += mk;
        }
    }
    rnum[tid] = num; rden[tid] = den;
    __syncthreads();
    for (int s = 64; s > 0; s >>= 1) {
        if (tid < s) { rnum[tid] += rnum[tid+s]; rden[tid] += rden[tid+s]; }
        __syncthreads();
    }
    if (tid == 0) {
        int it = z >> 2;
        atomicAdd(&g_num[it], rnum[0]);
        atomicAdd(&g_den[it], rden[0]);
    }
}

// ---------------- finalize: mean over iterations of num/den ----------------
__global__ void finalize_kernel(float* out) {
    if (threadIdx.x == 0 && blockIdx.x == 0) {
        float s = 0.0f;
        for (int i = 0; i < IT; i++) s += g_num[i] / g_den[i];
        out[0] = s / (float)IT;
    }
}

// ---------------- launch ----------------
extern "C" void kernel_launch(void* const* d_in, const int* in_sizes, int n_in,
                              void* d_out, int out_size) {
    const float* x    = (const float*)d_in[0];
    const float* d    = (const float*)d_in[1];
    const float* gts  = (const float*)d_in[2];
    const float* rnd  = (const float*)d_in[3];
    const float* Watt = (const float*)d_in[4];
    const float* batt = (const float*)d_in[5];
    const float* Wp   = (const float*)d_in[6];
    const float* bp   = (const float*)d_in[7];
    float* out = (float*)d_out;

    float *xt, *dt;
    cudaGetSymbolAddress((void**)&xt, g_xt);
    cudaGetSymbolAddress((void**)&dt, g_dt);

    zero_kernel<<<1, 32>>>();
    transpose_kernel<<<dim3(GH*GW/32, NB), dim3(32, 8)>>>(x, xt, GH*GW);
    transpose_kernel<<<dim3(SH*SW/32, NB), dim3(32, 8)>>>(d, dt, SH*SW);
    pool_kernel<<<(IT*NB*SH*SW + 255)/256, 256>>>(gts, rnd);
    sample_kernel<<<(IT*NB*SH*SW*32)/256, 256>>>();
    conv_att_kernel<<<dim3(SW/32, SH/8, IT*NB), 128>>>(Watt, batt);
    conv_post_loss_kernel<<<dim3(SW/32, SH/8, IT*NB), 128>>>(Wp, bp);
    finalize_kernel<<<1, 32>>>(out);
}

// round 13
// speedup vs baseline: 2.9781x; 1.1807x over previous
#include <cuda_runtime.h>
#include <cuda_bf16.h>
#include <math.h>
#include <cstdint>

#define IT 20
#define NB 4
#define GH 480
#define GW 640
#define SH 120
#define SW 160
#define NC 32

typedef unsigned long long u64;

// ---------------- static device scratch (no runtime allocation) ----------------
__device__ uint32_t g_xtb[NB*GH*GW*16];             // x transposed to NHWC bf16x2 (78 MB)
__device__ float    g_dt[NB*SH*SW*NC];              // d transposed to NHWC f32    (9.8 MB)
__device__ float    g_rg[IT*NB*SH*SW];              // pooled gt
__device__ float    g_ixb[IT*NB*SH*SW];             // sample x pixel coord
__device__ float    g_iyb[IT*NB*SH*SW];             // sample y pixel coord
__device__ uint32_t g_feat[IT*NB*SH*SW*16];         // sampled features NHWC bf16x2 (98 MB)
__device__ uint32_t g_attd[IT*NB*SH*SW*16];         // sigmoid(conv)*d NHWC bf16x2  (98 MB)
__device__ float    g_num[IT];
__device__ float    g_den[IT];

// ---------------- helpers ----------------
__device__ __forceinline__ uint32_t pack_bf16(float lo, float hi) {
    uint32_t r;
    asm("cvt.rn.bf16x2.f32 %0, %1, %2;" : "=r"(r) : "f"(hi), "f"(lo));
    return r;
}
__device__ __forceinline__ float2 unpack_bf16(uint32_t u) {
    __nv_bfloat162 h = *reinterpret_cast<const __nv_bfloat162*>(&u);
    return make_float2(__bfloat162float(h.x), __bfloat162float(h.y));
}
__device__ __forceinline__ uint32_t smem_to_u32(const void* p) {
    uint32_t a;
    asm("{ .reg .u64 t; cvta.to.shared.u64 t, %1; cvt.u32.u64 %0, t; }" : "=r"(a) : "l"(p));
    return a;
}
__device__ __forceinline__ void ldmatrix_x4(uint32_t* r, uint32_t addr) {
    asm volatile("ldmatrix.sync.aligned.m8n8.x4.shared.b16 {%0, %1, %2, %3}, [%4];"
        : "=r"(r[0]), "=r"(r[1]), "=r"(r[2]), "=r"(r[3]) : "r"(addr));
}
__device__ __forceinline__ void mma_bf16(float* c, const uint32_t* a, const uint32_t* b) {
    asm volatile("mma.sync.aligned.m16n8k16.row.col.f32.bf16.bf16.f32 "
        "{%0, %1, %2, %3}, {%4, %5, %6, %7}, {%8, %9}, {%0, %1, %2, %3};"
        : "+f"(c[0]), "+f"(c[1]), "+f"(c[2]), "+f"(c[3])
        : "r"(a[0]), "r"(a[1]), "r"(a[2]), "r"(a[3]), "r"(b[0]), "r"(b[1]));
}

// ---------------- zero per-iteration accumulators ----------------
__global__ void zero_kernel() {
    int t = threadIdx.x;
    if (t < IT) { g_num[t] = 0.0f; g_den[t] = 0.0f; }
}

// ---------------- NCHW f32 -> NHWC bf16x2 transpose (C=32), per batch (for x) ----------------
__global__ void transpose_bf16_kernel(const float* __restrict__ src, uint32_t* __restrict__ dst, int S) {
    __shared__ float t[32][33];
    int s0 = blockIdx.x * 32;
    const float* sb = src + (size_t)blockIdx.y * NC * S;
    uint32_t*    db = dst + (size_t)blockIdx.y * S * 16;
    int lx = threadIdx.x, ly = threadIdx.y;
    #pragma unroll
    for (int cc = 0; cc < 4; cc++) {
        int c = ly + cc * 8;
        t[c][lx] = sb[(size_t)c * S + s0 + lx];
    }
    __syncthreads();
    if (lx < 16) {
        #pragma unroll
        for (int cc = 0; cc < 4; cc++) {
            int sr = ly + cc * 8;
            db[(size_t)(s0 + sr) * 16 + lx] = pack_bf16(t[2*lx][sr], t[2*lx+1][sr]);
        }
    }
}

// ---------------- NCHW -> NHWC f32 transpose (C=32), per batch (for d) ----------------
__global__ void transpose_kernel(const float* __restrict__ src, float* __restrict__ dst, int S) {
    __shared__ float t[32][33];
    int s0 = blockIdx.x * 32;
    const float* sb = src + (size_t)blockIdx.y * NC * S;
    float*       db = dst + (size_t)blockIdx.y * S * NC;
    int lx = threadIdx.x, ly = threadIdx.y;
    #pragma unroll
    for (int cc = 0; cc < 4; cc++) {
        int c = ly + cc * 8;
        t[c][lx] = sb[(size_t)c * S + s0 + lx];
    }
    __syncthreads();
    #pragma unroll
    for (int cc = 0; cc < 4; cc++) {
        int sr = ly + cc * 8;
        db[(size_t)(s0 + sr) * NC + lx] = t[lx][sr];
    }
}

// ---------------- random pooling + sample-coordinate computation ----------------
__global__ void pool_kernel(const float* __restrict__ gts, const float* __restrict__ rnd) {
    int tid = blockIdx.x * blockDim.x + threadIdx.x;
    if (tid >= IT*NB*SH*SW) return;
    int x  = tid % SW;  int t1 = tid / SW;
    int y  = t1 % SH;   int t2 = t1 / SH;
    int b  = t2 % NB;   int it = t2 / NB;
    const float* gp = gts + b * GH * GW;
    const float* rp = rnd + (it * NB + b) * GH * GW;

    float best = -1.0f;
    int srow = y*4, scol = x*4;
    #pragma unroll
    for (int bi = 0; bi < 4; bi++) {
        int row = y*4 + bi;
        #pragma unroll
        for (int bj = 0; bj < 4; bj++) {
            int col = x*4 + bj;
            float g  = gp[row*GW + col];
            float rm = (g > 0.1f) ? rp[row*GW + col] : 0.0f;
            if (rm > best) { best = rm; srow = row; scol = col; }
        }
    }
    float rv = gp[srow*GW + scol];
    if (rv < 0.1f) rv = 0.0f;
    g_rg[tid] = rv;

    int index = srow*GW + scol + 1282;   // bias = 2 + 2*640
    float fx = (float)(index % GW);
    float fy = (float)(index / GW);
    float gx = 2.0f * (fx / (float)GW - 0.5f);
    float gy = 2.0f * (fy / (float)GH - 0.5f);
    g_ixb[tid] = (gx + 1.0f) * 0.5f * (float)(GW - 1);
    g_iyb[tid] = (gy + 1.0f) * 0.5f * (float)(GH - 1);
}

// ---------------- bilinear grid-sample, L2-reuse tiled ----------------
// grid (SW/16, SH/8, NB); block 256 = 16 point-slots x 16 lanes (lane = channel-pair).
// All 20 iterations for this spatial tile are processed inside the block, so the
// ~153 KB x-region serves 20x4 corner gathers from L2.
__global__ __launch_bounds__(256) void sample_kernel() {
    int b = blockIdx.z;
    int slot   = threadIdx.x >> 4;
    int lane16 = threadIdx.x & 15;
    const uint32_t* xb = g_xtb + (size_t)b * GH * GW * 16;

    #pragma unroll 1
    for (int r = 0; r < 160; r++) {
        int idx = r*16 + slot;           // 0..2559 = 20 it x 128 points
        int it = idx >> 7;
        int p  = idx & 127;
        int py = p >> 4, px = p & 15;
        int gy = blockIdx.y*8 + py, gx = blockIdx.x*16 + px;
        int pid = ((it*NB + b)*SH + gy)*SW + gx;

        float ix = g_ixb[pid], iy = g_iyb[pid];
        float x0f = floorf(ix), y0f = floorf(iy);
        float wx = ix - x0f, wy = iy - y0f;
        int x0 = (int)x0f, y0 = (int)y0f;

        float acc0 = 0.0f, acc1 = 0.0f;
#define CORNER(XC, YC, WG) {                                                \
            int xc = (XC), yc = (YC);                                       \
            bool v = (xc >= 0) && (xc <= GW-1) && (yc >= 0) && (yc <= GH-1);\
            int xi = min(max(xc, 0), GW-1);                                 \
            int yi = min(max(yc, 0), GH-1);                                 \
            float2 val = unpack_bf16(xb[(yi*GW + xi)*16 + lane16]);         \
            float w = (v ? (WG) : 0.0f);                                    \
            acc0 += val.x * w;                                              \
            acc1 += val.y * w;                                              \
        }
        CORNER(x0,   y0,   (1.0f-wx)*(1.0f-wy));
        CORNER(x0+1, y0,   wx*(1.0f-wy));
        CORNER(x0,   y0+1, (1.0f-wx)*wy);
        CORNER(x0+1, y0+1, wx*wy);
#undef CORNER
        g_feat[(size_t)pid*16 + lane16] = pack_bf16(acc0, acc1);
    }
}

// ---------------- conv3x3 (32->32) via HMMA + sigmoid*d -> attd (bf16) ----------------
#define PXS 80                                     // pixel record stride in bytes (32 bf16 + pad)
__global__ __launch_bounds__(128) void conv_att_kernel(const float* __restrict__ Watt,
                                                       const float* __restrict__ batt) {
    __shared__ __align__(16) char s_tile[10*34*PXS];          // 27200 B, im2col window
    __shared__ __align__(16) __nv_bfloat16 s_w[32][296];      // k-major weights

    int tid = threadIdx.x;
    int wid = tid >> 5, lane = tid & 31;
    int bx = blockIdx.x, by = blockIdx.y, z = blockIdx.z;

    const uint32_t* fz = g_feat + (size_t)z * SH * SW * 16;
    int gy0 = by*8 - 1, gx0 = bx*32 - 1;
    for (int idx = tid; idx < 10*34*16; idx += 128) {
        int w = idx & 15; int rem = idx >> 4;
        int xx = rem % 34; int yy = rem / 34;
        int ggy = gy0 + yy, ggx = gx0 + xx;
        uint32_t v = 0;
        if (ggy >= 0 && ggy < SH && ggx >= 0 && ggx < SW)
            v = fz[(ggy*SW + ggx)*16 + w];
        *(uint32_t*)(s_tile + (yy*34 + xx)*PXS + w*4) = v;
    }
    for (int idx = tid; idx < 32*288; idx += 128) {
        int co = idx / 288; int k = idx - co*288;
        int tap = k >> 5, ci = k & 31;
        s_w[co][k] = __float2bfloat16(Watt[(co*32 + ci)*9 + tap]);
    }
    __syncthreads();

    int g  = lane >> 2, t2 = lane & 3;
    uint32_t bf[18][2];
    #pragma unroll
    for (int j = 0; j < 18; j++) {
        int k0 = j*16 + t2*2;
        bf[j][0] = *(const uint32_t*)&s_w[wid*8 + g][k0];
        bf[j][1] = *(const uint32_t*)&s_w[wid*8 + g][k0 + 8];
    }

    int m_row = (lane & 7) + ((lane & 8) ? 8 : 0);
    uint32_t k8 = (lane & 16) ? 16u : 0u;
    uint32_t tb = smem_to_u32(s_tile);
    int b = z & 3;
    int co0 = wid*8 + t2*2;
    float bt0 = batt[co0], bt1 = batt[co0+1];

    #pragma unroll 1
    for (int mp = 0; mp < 8; mp++) {
        int p0 = mp*32 + m_row;
        int p1 = p0 + 16;
        uint32_t a0base = tb + (uint32_t)(((p0 >> 5)*34 + (p0 & 31))*PXS) + k8;
        uint32_t a1base = tb + (uint32_t)(((p1 >> 5)*34 + (p1 & 31))*PXS) + k8;

        float acc0[4] = {0,0,0,0};
        float acc1[4] = {0,0,0,0};
        #pragma unroll
        for (int t = 0; t < 9; t++) {
            uint32_t toff = (uint32_t)(((t/3)*34 + (t%3))*PXS);
            #pragma unroll
            for (int h = 0; h < 2; h++) {
                int j = t*2 + h;
                uint32_t A0[4], A1[4];
                ldmatrix_x4(A0, a0base + toff + h*32);
                ldmatrix_x4(A1, a1base + toff + h*32);
                mma_bf16(acc0, A0, bf[j]);
                mma_bf16(acc1, A1, bf[j]);
            }
        }

        #pragma unroll
        for (int half = 0; half < 2; half++) {
            float* acc = half ? acc1 : acc0;
            int pb = mp*32 + half*16;
            #pragma unroll
            for (int r = 0; r < 2; r++) {
                int p = pb + g + r*8;
                int gy = by*8 + (p >> 5);
                int gx = bx*32 + (p & 31);
                float2 dv = *(const float2*)&g_dt[((size_t)(b*SH + gy)*SW + gx)*NC + co0];
                float v0 = acc[r*2+0] + bt0;
                float v1 = acc[r*2+1] + bt1;
                float a0 = dv.x / (1.0f + __expf(-v0));
                float a1 = dv.y / (1.0f + __expf(-v1));
                g_attd[((size_t)z*SH*SW + gy*SW + gx)*16 + (co0 >> 1)] = pack_bf16(a0, a1);
            }
        }
    }
}

// ---------------- conv3x3 (32->4) via HMMA + log-grads + masked smooth-L1 + reduction ----------------
__global__ __launch_bounds__(128) void conv_post_loss_kernel(const float* __restrict__ Wp,
                                                             const float* __restrict__ bp) {
    __shared__ __align__(16) char s_tile[10*34*PXS];
    __shared__ __align__(16) __nv_bfloat16 s_wp[8][296];
    __shared__ float s_ds[256][4];
    __shared__ float rnum[128];
    __shared__ float rden[128];

    int tid = threadIdx.x;
    int wid = tid >> 5, lane = tid & 31;
    int bx = blockIdx.x, by = blockIdx.y, z = blockIdx.z;

    const uint32_t* az = g_attd + (size_t)z * SH * SW * 16;
    int gy0 = by*8 - 1, gx0 = bx*32 - 1;
    for (int idx = tid; idx < 10*34*16; idx += 128) {
        int w = idx & 15; int rem = idx >> 4;
        int xx = rem % 34; int yy = rem / 34;
        int ggy = gy0 + yy, ggx = gx0 + xx;
        uint32_t v = 0;
        if (ggy >= 0 && ggy < SH && ggx >= 0 && ggx < SW)
            v = az[(ggy*SW + ggx)*16 + w];
        *(uint32_t*)(s_tile + (yy*34 + xx)*PXS + w*4) = v;
    }
    for (int idx = tid; idx < 8*288; idx += 128) {
        int co = idx / 288; int k = idx - co*288;
        int tap = k >> 5, ci = k & 31;
        s_wp[co][k] = (co < 4) ? __float2bfloat16(Wp[(co*32 + ci)*9 + tap])
                               : __float2bfloat16(0.0f);
    }
    __syncthreads();

    int g  = lane >> 2, t2 = lane & 3;
    uint32_t bf[18][2];
    #pragma unroll
    for (int j = 0; j < 18; j++) {
        int k0 = j*16 + t2*2;
        bf[j][0] = *(const uint32_t*)&s_wp[g][k0];
        bf[j][1] = *(const uint32_t*)&s_wp[g][k0 + 8];
    }

    int m_row = (lane & 7) + ((lane & 8) ? 8 : 0);
    uint32_t k8 = (lane & 16) ? 16u : 0u;
    uint32_t tb = smem_to_u32(s_tile);

    #pragma unroll 1
    for (int q = 0; q < 4; q++) {
        int mt = wid*4 + q;
        int p0 = mt*16 + m_row;
        uint32_t abase = tb + (uint32_t)(((p0 >> 5)*34 + (p0 & 31))*PXS) + k8;

        float acc[4] = {0,0,0,0};
        #pragma unroll
        for (int t = 0; t < 9; t++) {
            uint32_t toff = (uint32_t)(((t/3)*34 + (t%3))*PXS);
            #pragma unroll
            for (int h = 0; h < 2; h++) {
                uint32_t A[4];
                ldmatrix_x4(A, abase + toff + h*32);
                mma_bf16(acc, A, bf[t*2 + h]);
            }
        }
        if (t2 < 2) {
            int pA = mt*16 + g;
            int pB = pA + 8;
            s_ds[pA][t2*2+0] = acc[0];
            s_ds[pA][t2*2+1] = acc[1];
            s_ds[pB][t2*2+0] = acc[2];
            s_ds[pB][t2*2+1] = acc[3];
        }
    }
    __syncthreads();

    const float* rz = g_rg + z * SH * SW;
    const int dys[4] = {0, 1, 1, 1};
    const int dxs[4] = {1, 1, 0, -1};
    float num = 0.0f, den = 0.0f;
    #pragma unroll
    for (int pp = 0; pp < 2; pp++) {
        int p = tid + pp*128;
        int gy = by*8 + (p >> 5);
        int gx = bx*32 + (p & 31);
        float4 dsv = *(const float4*)&s_ds[p][0];
        float ds[4] = {dsv.x + bp[0], dsv.y + bp[1], dsv.z + bp[2], dsv.w + bp[3]};

        float rv = rz[gy*SW + gx];
        float lc = logf(rv + 1e-6f);
        bool  mc = rv > 0.1f;
        #pragma unroll
        for (int gI = 0; gI < 4; gI++) {
            int ny = gy + dys[gI], nx = gx + dxs[gI];
            bool inb = (ny < SH) && (nx >= 0) && (nx < SW);
            float nv = inb ? rz[ny*SW + nx] : 0.0f;
            float gg = lc - logf(nv + 1e-6f);
            float mk = (mc && (nv > 0.1f)) ? 1.0f : 0.0f;
            float a  = fabsf(ds[gI] - gg);
            float sl1 = (a < 0.01f) ? (0.5f * a * a / 0.01f) : (a - 0.005f);
            num += sl1 * mk;
            den += mk;
        }
    }
    rnum[tid] = num; rden[tid] = den;
    __syncthreads();
    for (int s = 64; s > 0; s >>= 1) {
        if (tid < s) { rnum[tid] += rnum[tid+s]; rden[tid] += rden[tid+s]; }
        __syncthreads();
    }
    if (tid == 0) {
        int it = z >> 2;
        atomicAdd(&g_num[it], rnum[0]);
        atomicAdd(&g_den[it], rden[0]);
    }
}

// ---------------- finalize: mean over iterations of num/den ----------------
__global__ void finalize_kernel(float* out) {
    if (threadIdx.x == 0 && blockIdx.x == 0) {
        float s = 0.0f;
        for (int i = 0; i < IT; i++) s += g_num[i] / g_den[i];
        out[0] = s / (float)IT;
    }
}

// ---------------- launch ----------------
extern "C" void kernel_launch(void* const* d_in, const int* in_sizes, int n_in,
                              void* d_out, int out_size) {
    const float* x    = (const float*)d_in[0];
    const float* d    = (const float*)d_in[1];
    const float* gts  = (const float*)d_in[2];
    const float* rnd  = (const float*)d_in[3];
    const float* Watt = (const float*)d_in[4];
    const float* batt = (const float*)d_in[5];
    const float* Wp   = (const float*)d_in[6];
    const float* bp   = (const float*)d_in[7];
    float* out = (float*)d_out;

    uint32_t* xtb;
    float* dt;
    cudaGetSymbolAddress((void**)&xtb, g_xtb);
    cudaGetSymbolAddress((void**)&dt, g_dt);

    zero_kernel<<<1, 32>>>();
    transpose_bf16_kernel<<<dim3(GH*GW/32, NB), dim3(32, 8)>>>(x, xtb, GH*GW);
    transpose_kernel<<<dim3(SH*SW/32, NB), dim3(32, 8)>>>(d, dt, SH*SW);
    pool_kernel<<<(IT*NB*SH*SW + 255)/256, 256>>>(gts, rnd);
    sample_kernel<<<dim3(SW/16, SH/8, NB), 256>>>();
    conv_att_kernel<<<dim3(SW/32, SH/8, IT*NB), 128>>>(Watt, batt);
    conv_post_loss_kernel<<<dim3(SW/32, SH/8, IT*NB), 128>>>(Wp, bp);
    finalize_kernel<<<1, 32>>>(out);
}